// round 1
// baseline (speedup 1.0000x reference)
#include <cuda_runtime.h>
#include <cstdint>

#define NB 4096      // pixels per batch (64*64)
#define MB 1024      // pooled pixels per batch (32*32)
#define BATCH 8
#define NPIX (BATCH*NB)   // 32768

// ---------------- scratch (static device allocations) ----------------
__device__ float g_g[NPIX*32];       // g projection  [B*N, 32]
__device__ float g_fpre[NPIX*32];    // f pre-pool    [B*N, 32]
__device__ float g_hpre[NPIX*128];   // h pre-pool    [B*N, 128]
__device__ float g_f[BATCH*MB*32];   // f pooled      [B*M, 32]
__device__ float g_h[BATCH*MB*128];  // h pooled      [B*M, 128]
__device__ float g_o[NPIX*128];      // attention out [B*N, 128]

// ---------------- linear: Y[64rows, NO] = X[64,256] @ W[256,NO] + b ----------------
template<int NO>
__global__ void __launch_bounds__(256) linear_k(const float* __restrict__ X,
                                                const float* __restrict__ W,
                                                const float* __restrict__ bias,
                                                float* __restrict__ Y)
{
    constexpr int NG = NO / 16;            // float4 groups per thread (strided by 16 cols)
    __shared__ float Xs[64][33];
    __shared__ float Ws[32][NO + 4];
    const int tid  = threadIdx.x;
    const int row0 = blockIdx.x * 64;
    const int r    = tid >> 2;             // 0..63
    const int c0   = (tid & 3) * 4;        // base col; thread owns c0+16*j .. +3

    float4 acc[NG];
    #pragma unroll
    for (int j = 0; j < NG; j++) acc[j] = make_float4(0.f, 0.f, 0.f, 0.f);

    for (int kc = 0; kc < 256; kc += 32) {
        #pragma unroll
        for (int t = 0; t < 2; t++) {
            int idx = t * 256 + tid;
            int rr = idx >> 3, cc = (idx & 7) * 4;
            float4 v = *(const float4*)(X + (size_t)(row0 + rr) * 256 + kc + cc);
            Xs[rr][cc] = v.x; Xs[rr][cc+1] = v.y; Xs[rr][cc+2] = v.z; Xs[rr][cc+3] = v.w;
        }
        constexpr int WT = (32 * NO / 4) / 256;   // 1 (NO=32) or 4 (NO=128)
        #pragma unroll
        for (int t = 0; t < WT; t++) {
            int idx = t * 256 + tid;
            int kk = idx / (NO / 4), cc = (idx % (NO / 4)) * 4;
            float4 v = *(const float4*)(W + (size_t)(kc + kk) * NO + cc);
            Ws[kk][cc] = v.x; Ws[kk][cc+1] = v.y; Ws[kk][cc+2] = v.z; Ws[kk][cc+3] = v.w;
        }
        __syncthreads();
        #pragma unroll
        for (int k = 0; k < 32; k++) {
            float a = Xs[r][k];
            #pragma unroll
            for (int j = 0; j < NG; j++) {
                float4 w = *(const float4*)(&Ws[k][c0 + 16 * j]);
                acc[j].x += a * w.x; acc[j].y += a * w.y;
                acc[j].z += a * w.z; acc[j].w += a * w.w;
            }
        }
        __syncthreads();
    }
    #pragma unroll
    for (int j = 0; j < NG; j++) {
        int c = c0 + 16 * j;
        float4 bb = *(const float4*)(bias + c);
        float4 v = make_float4(acc[j].x + bb.x, acc[j].y + bb.y,
                               acc[j].z + bb.z, acc[j].w + bb.w);
        *(float4*)(Y + (size_t)(row0 + r) * NO + c) = v;
    }
}

// ---------------- 2x2 maxpool (H,W even -> exact) ----------------
template<int NO>
__global__ void pool_k(const float* __restrict__ src, float* __restrict__ dst)
{
    int idx = blockIdx.x * blockDim.x + threadIdx.x;   // float4 index over [B, MB, NO]
    const int total = BATCH * MB * (NO / 4);
    if (idx >= total) return;
    int c4 = idx % (NO / 4);
    int m  = (idx / (NO / 4)) % MB;
    int b  = idx / ((NO / 4) * MB);
    int h2 = m >> 5, w2 = m & 31;
    size_t p00 = ((size_t)(b * 64 + h2 * 2) * 64 + w2 * 2);
    float4 a = ((const float4*)(src + p00 * NO))[c4];
    float4 bq = ((const float4*)(src + (p00 + 1) * NO))[c4];
    float4 c = ((const float4*)(src + (p00 + 64) * NO))[c4];
    float4 d = ((const float4*)(src + (p00 + 65) * NO))[c4];
    float4 r;
    r.x = fmaxf(fmaxf(a.x, bq.x), fmaxf(c.x, d.x));
    r.y = fmaxf(fmaxf(a.y, bq.y), fmaxf(c.y, d.y));
    r.z = fmaxf(fmaxf(a.z, bq.z), fmaxf(c.z, d.z));
    r.w = fmaxf(fmaxf(a.w, bq.w), fmaxf(c.w, d.w));
    ((float4*)dst)[idx] = r;
}

// ---------------- flash attention: per block 64 queries x 1024 keys ----------------
// thread grid 16x16: thread (ty,tx) owns S rows ty*4..+3, key cols tx+16j (j<4),
// O cols tx*4..+3 (half0) and 64+tx*4..+3 (half1).
__global__ void __launch_bounds__(256) attn_k(const float* __restrict__ G,
                                              const float* __restrict__ F,
                                              const float* __restrict__ H,
                                              float* __restrict__ O)
{
    __shared__ float Gs[64 * 36];
    __shared__ float FPs[64 * 68];   // F tile (cols 0..31) then P tile (cols 0..63)
    __shared__ float Hs[64 * 68];    // one 64-col half of H tile
    const int tid = threadIdx.x;
    const int tx = tid & 15, ty = tid >> 4;
    const int b  = blockIdx.x >> 6;
    const int q0 = (blockIdx.x & 63) * 64;
    const float* Gb = G + ((size_t)b * NB + q0) * 32;
    const float* Fb = F + (size_t)b * MB * 32;
    const float* Hb = H + (size_t)b * MB * 128;

    #pragma unroll
    for (int t = 0; t < 2; t++) {
        int idx = t * 256 + tid;
        int rr = idx >> 3, cc = (idx & 7) * 4;
        float4 v = *(const float4*)(Gb + (size_t)rr * 32 + cc);
        float* d = Gs + rr * 36 + cc;
        d[0] = v.x; d[1] = v.y; d[2] = v.z; d[3] = v.w;
    }

    float m[4], l[4];
    float4 oA[4], oB[4];
    #pragma unroll
    for (int i = 0; i < 4; i++) {
        m[i] = -1e30f; l[i] = 0.f;
        oA[i] = make_float4(0.f, 0.f, 0.f, 0.f);
        oB[i] = make_float4(0.f, 0.f, 0.f, 0.f);
    }

    for (int kt = 0; kt < 16; kt++) {
        const int k0 = kt * 64;
        __syncthreads();   // prior PV done before overwriting FPs/Hs
        // F tile -> FPs cols 0..31
        #pragma unroll
        for (int t = 0; t < 2; t++) {
            int idx = t * 256 + tid;
            int rr = idx >> 3, cc = (idx & 7) * 4;
            float4 v = *(const float4*)(Fb + (size_t)(k0 + rr) * 32 + cc);
            float* d = FPs + rr * 68 + cc;
            d[0] = v.x; d[1] = v.y; d[2] = v.z; d[3] = v.w;
        }
        // H tile half 0 (cols 0..63)
        #pragma unroll
        for (int t = 0; t < 4; t++) {
            int idx = t * 256 + tid;
            int rr = idx >> 4, cc = (idx & 15) * 4;
            float4 v = *(const float4*)(Hb + (size_t)(k0 + rr) * 128 + cc);
            float* d = Hs + rr * 68 + cc;
            d[0] = v.x; d[1] = v.y; d[2] = v.z; d[3] = v.w;
        }
        __syncthreads();

        // S = G @ F^T  (4x4 per thread, key col = tx + 16*j)
        float s[4][4];
        #pragma unroll
        for (int i = 0; i < 4; i++)
            #pragma unroll
            for (int j = 0; j < 4; j++) s[i][j] = 0.f;
        #pragma unroll
        for (int k = 0; k < 32; k += 4) {
            float4 gv[4], fv[4];
            #pragma unroll
            for (int i = 0; i < 4; i++)
                gv[i] = *(const float4*)(Gs + (ty * 4 + i) * 36 + k);
            #pragma unroll
            for (int j = 0; j < 4; j++)
                fv[j] = *(const float4*)(FPs + (tx + 16 * j) * 68 + k);
            #pragma unroll
            for (int i = 0; i < 4; i++)
                #pragma unroll
                for (int j = 0; j < 4; j++)
                    s[i][j] += gv[i].x * fv[j].x + gv[i].y * fv[j].y
                             + gv[i].z * fv[j].z + gv[i].w * fv[j].w;
        }

        // online softmax update
        #pragma unroll
        for (int i = 0; i < 4; i++) {
            float tm = fmaxf(fmaxf(s[i][0], s[i][1]), fmaxf(s[i][2], s[i][3]));
            #pragma unroll
            for (int off = 1; off < 16; off <<= 1)
                tm = fmaxf(tm, __shfl_xor_sync(0xffffffffu, tm, off));
            float mn = fmaxf(m[i], tm);
            float corr = __expf(m[i] - mn);
            m[i] = mn;
            float rs = 0.f;
            #pragma unroll
            for (int j = 0; j < 4; j++) { s[i][j] = __expf(s[i][j] - mn); rs += s[i][j]; }
            #pragma unroll
            for (int off = 1; off < 16; off <<= 1)
                rs += __shfl_xor_sync(0xffffffffu, rs, off);
            l[i] = l[i] * corr + rs;
            oA[i].x *= corr; oA[i].y *= corr; oA[i].z *= corr; oA[i].w *= corr;
            oB[i].x *= corr; oB[i].y *= corr; oB[i].z *= corr; oB[i].w *= corr;
        }
        __syncthreads();   // S reads of FPs done
        // store P
        #pragma unroll
        for (int i = 0; i < 4; i++)
            #pragma unroll
            for (int j = 0; j < 4; j++)
                FPs[(ty * 4 + i) * 68 + tx + 16 * j] = s[i][j];
        __syncthreads();

        // PV half 0
        #pragma unroll
        for (int k = 0; k < 64; k += 4) {
            float4 h0 = *(const float4*)(Hs + (k + 0) * 68 + tx * 4);
            float4 h1 = *(const float4*)(Hs + (k + 1) * 68 + tx * 4);
            float4 h2 = *(const float4*)(Hs + (k + 2) * 68 + tx * 4);
            float4 h3 = *(const float4*)(Hs + (k + 3) * 68 + tx * 4);
            #pragma unroll
            for (int i = 0; i < 4; i++) {
                float4 p = *(const float4*)(FPs + (ty * 4 + i) * 68 + k);
                oA[i].x += p.x * h0.x + p.y * h1.x + p.z * h2.x + p.w * h3.x;
                oA[i].y += p.x * h0.y + p.y * h1.y + p.z * h2.y + p.w * h3.y;
                oA[i].z += p.x * h0.z + p.y * h1.z + p.z * h2.z + p.w * h3.z;
                oA[i].w += p.x * h0.w + p.y * h1.w + p.z * h2.w + p.w * h3.w;
            }
        }
        __syncthreads();
        // H tile half 1 (cols 64..127)
        #pragma unroll
        for (int t = 0; t < 4; t++) {
            int idx = t * 256 + tid;
            int rr = idx >> 4, cc = (idx & 15) * 4;
            float4 v = *(const float4*)(Hb + (size_t)(k0 + rr) * 128 + 64 + cc);
            float* d = Hs + rr * 68 + cc;
            d[0] = v.x; d[1] = v.y; d[2] = v.z; d[3] = v.w;
        }
        __syncthreads();
        // PV half 1
        #pragma unroll
        for (int k = 0; k < 64; k += 4) {
            float4 h0 = *(const float4*)(Hs + (k + 0) * 68 + tx * 4);
            float4 h1 = *(const float4*)(Hs + (k + 1) * 68 + tx * 4);
            float4 h2 = *(const float4*)(Hs + (k + 2) * 68 + tx * 4);
            float4 h3 = *(const float4*)(Hs + (k + 3) * 68 + tx * 4);
            #pragma unroll
            for (int i = 0; i < 4; i++) {
                float4 p = *(const float4*)(FPs + (ty * 4 + i) * 68 + k);
                oB[i].x += p.x * h0.x + p.y * h1.x + p.z * h2.x + p.w * h3.x;
                oB[i].y += p.x * h0.y + p.y * h1.y + p.z * h2.y + p.w * h3.y;
                oB[i].z += p.x * h0.z + p.y * h1.z + p.z * h2.z + p.w * h3.z;
                oB[i].w += p.x * h0.w + p.y * h1.w + p.z * h2.w + p.w * h3.w;
            }
        }
    }

    // epilogue: normalize and store
    #pragma unroll
    for (int i = 0; i < 4; i++) {
        float inv = 1.f / l[i];
        float4 a = oA[i], c = oB[i];
        a.x *= inv; a.y *= inv; a.z *= inv; a.w *= inv;
        c.x *= inv; c.y *= inv; c.z *= inv; c.w *= inv;
        size_t row = (size_t)b * NB + q0 + ty * 4 + i;
        *(float4*)(O + row * 128 + tx * 4) = a;
        *(float4*)(O + row * 128 + 64 + tx * 4) = c;
    }
}

// ---------------- out = gamma * (o @ Wo + bo) + x ----------------
__global__ void __launch_bounds__(256) out_k(const float* __restrict__ Oin,
                                             const float* __restrict__ Wo,
                                             const float* __restrict__ bo,
                                             const float* __restrict__ x,
                                             const float* __restrict__ gamma,
                                             float* __restrict__ out)
{
    __shared__ float Os[32][33];
    __shared__ float Ws[32][260];
    const int tid  = threadIdx.x;
    const int row0 = blockIdx.x * 32;
    const int r    = tid & 31;
    const int c0   = (tid >> 5) * 32;
    float4 acc[8];
    #pragma unroll
    for (int j = 0; j < 8; j++) acc[j] = make_float4(0.f, 0.f, 0.f, 0.f);

    for (int kc = 0; kc < 128; kc += 32) {
        {
            int rr = tid >> 3, cc = (tid & 7) * 4;
            float4 v = *(const float4*)(Oin + (size_t)(row0 + rr) * 128 + kc + cc);
            Os[rr][cc] = v.x; Os[rr][cc+1] = v.y; Os[rr][cc+2] = v.z; Os[rr][cc+3] = v.w;
        }
        #pragma unroll
        for (int t = 0; t < 8; t++) {
            int idx = t * 256 + tid;
            int kk = idx >> 6, cc = (idx & 63) * 4;
            float4 v = *(const float4*)(Wo + (size_t)(kc + kk) * 256 + cc);
            Ws[kk][cc] = v.x; Ws[kk][cc+1] = v.y; Ws[kk][cc+2] = v.z; Ws[kk][cc+3] = v.w;
        }
        __syncthreads();
        #pragma unroll
        for (int k = 0; k < 32; k++) {
            float a = Os[r][k];
            #pragma unroll
            for (int j = 0; j < 8; j++) {
                float4 w = *(const float4*)(&Ws[k][c0 + 4 * j]);
                acc[j].x += a * w.x; acc[j].y += a * w.y;
                acc[j].z += a * w.z; acc[j].w += a * w.w;
            }
        }
        __syncthreads();
    }
    float gm = gamma[0];
    #pragma unroll
    for (int j = 0; j < 8; j++) {
        int c = c0 + 4 * j;
        float4 bb = *(const float4*)(bo + c);
        size_t off = (size_t)(row0 + r) * 256 + c;
        float4 xv = *(const float4*)(x + off);
        float4 v;
        v.x = gm * (acc[j].x + bb.x) + xv.x;
        v.y = gm * (acc[j].y + bb.y) + xv.y;
        v.z = gm * (acc[j].z + bb.z) + xv.z;
        v.w = gm * (acc[j].w + bb.w) + xv.w;
        *(float4*)(out + off) = v;
    }
}

// ---------------- launch ----------------
extern "C" void kernel_launch(void* const* d_in, const int* in_sizes, int n_in,
                              void* d_out, int out_size)
{
    (void)in_sizes; (void)n_in; (void)out_size;
    const float* x     = (const float*)d_in[0];
    const float* Wf    = (const float*)d_in[1];
    const float* bf    = (const float*)d_in[2];
    const float* Wg    = (const float*)d_in[3];
    const float* bg    = (const float*)d_in[4];
    const float* Wh    = (const float*)d_in[5];
    const float* bh    = (const float*)d_in[6];
    const float* Wo    = (const float*)d_in[7];
    const float* bo    = (const float*)d_in[8];
    const float* gamma = (const float*)d_in[9];
    float* out = (float*)d_out;

    float *pg, *pfpre, *phpre, *pf, *ph, *po;
    cudaGetSymbolAddress((void**)&pg,    g_g);
    cudaGetSymbolAddress((void**)&pfpre, g_fpre);
    cudaGetSymbolAddress((void**)&phpre, g_hpre);
    cudaGetSymbolAddress((void**)&pf,    g_f);
    cudaGetSymbolAddress((void**)&ph,    g_h);
    cudaGetSymbolAddress((void**)&po,    g_o);

    linear_k<32><<<NPIX / 64, 256>>>(x, Wg, bg, pg);
    linear_k<32><<<NPIX / 64, 256>>>(x, Wf, bf, pfpre);
    linear_k<128><<<NPIX / 64, 256>>>(x, Wh, bh, phpre);

    pool_k<32><<<(BATCH * MB * 8 + 255) / 256, 256>>>(pfpre, pf);
    pool_k<128><<<(BATCH * MB * 32 + 255) / 256, 256>>>(phpre, ph);

    attn_k<<<NPIX / 64, 256>>>(pg, pf, ph, po);

    out_k<<<NPIX / 32, 256>>>(po, Wo, bo, x, gamma, out);
}

// round 2
// speedup vs baseline: 1.0014x; 1.0014x over previous
#include <cuda_runtime.h>
#include <cstdint>

#define NB 4096      // pixels per batch (64*64)
#define MB 1024      // pooled pixels per batch (32*32)
#define BATCH 8
#define NPIX (BATCH*NB)   // 32768

// ---------------- scratch (static device allocations) ----------------
__device__ float g_g[NPIX*32];       // g projection  [B*N, 32]
__device__ float g_fpre[NPIX*32];    // f pre-pool    [B*N, 32]
__device__ float g_hpre[NPIX*128];   // h pre-pool    [B*N, 128]
__device__ float g_f[BATCH*MB*32];   // f pooled      [B*M, 32]
__device__ float g_h[BATCH*MB*128];  // h pooled      [B*M, 128]
__device__ float g_o[NPIX*128];      // attention out [B*N, 128]

// ---------------- linear: Y[64rows, NO] = X[64,256] @ W[256,NO] + b ----------------
template<int NO>
__global__ void __launch_bounds__(256) linear_k(const float* __restrict__ X,
                                                const float* __restrict__ W,
                                                const float* __restrict__ bias,
                                                float* __restrict__ Y)
{
    constexpr int NG = NO / 16;            // float4 groups per thread (strided by 16 cols)
    __shared__ float Xs[64][33];
    __shared__ float Ws[32][NO + 4];
    const int tid  = threadIdx.x;
    const int row0 = blockIdx.x * 64;
    const int r    = tid >> 2;             // 0..63
    const int c0   = (tid & 3) * 4;        // base col; thread owns c0+16*j .. +3

    float4 acc[NG];
    #pragma unroll
    for (int j = 0; j < NG; j++) acc[j] = make_float4(0.f, 0.f, 0.f, 0.f);

    for (int kc = 0; kc < 256; kc += 32) {
        #pragma unroll
        for (int t = 0; t < 2; t++) {
            int idx = t * 256 + tid;
            int rr = idx >> 3, cc = (idx & 7) * 4;
            float4 v = *(const float4*)(X + (size_t)(row0 + rr) * 256 + kc + cc);
            Xs[rr][cc] = v.x; Xs[rr][cc+1] = v.y; Xs[rr][cc+2] = v.z; Xs[rr][cc+3] = v.w;
        }
        constexpr int WT = (32 * NO / 4) / 256;   // 1 (NO=32) or 4 (NO=128)
        #pragma unroll
        for (int t = 0; t < WT; t++) {
            int idx = t * 256 + tid;
            int kk = idx / (NO / 4), cc = (idx % (NO / 4)) * 4;
            float4 v = *(const float4*)(W + (size_t)(kc + kk) * NO + cc);
            Ws[kk][cc] = v.x; Ws[kk][cc+1] = v.y; Ws[kk][cc+2] = v.z; Ws[kk][cc+3] = v.w;
        }
        __syncthreads();
        #pragma unroll
        for (int k = 0; k < 32; k++) {
            float a = Xs[r][k];
            #pragma unroll
            for (int j = 0; j < NG; j++) {
                float4 w = *(const float4*)(&Ws[k][c0 + 16 * j]);
                acc[j].x += a * w.x; acc[j].y += a * w.y;
                acc[j].z += a * w.z; acc[j].w += a * w.w;
            }
        }
        __syncthreads();
    }
    #pragma unroll
    for (int j = 0; j < NG; j++) {
        int c = c0 + 16 * j;
        float4 bb = *(const float4*)(bias + c);
        float4 v = make_float4(acc[j].x + bb.x, acc[j].y + bb.y,
                               acc[j].z + bb.z, acc[j].w + bb.w);
        *(float4*)(Y + (size_t)(row0 + r) * NO + c) = v;
    }
}

// ---------------- 2x2 maxpool (H,W even -> exact) ----------------
template<int NO>
__global__ void pool_k(const float* __restrict__ src, float* __restrict__ dst)
{
    int idx = blockIdx.x * blockDim.x + threadIdx.x;   // float4 index over [B, MB, NO]
    const int total = BATCH * MB * (NO / 4);
    if (idx >= total) return;
    int c4 = idx % (NO / 4);
    int m  = (idx / (NO / 4)) % MB;
    int b  = idx / ((NO / 4) * MB);
    int h2 = m >> 5, w2 = m & 31;
    size_t p00 = ((size_t)(b * 64 + h2 * 2) * 64 + w2 * 2);
    float4 a = ((const float4*)(src + p00 * NO))[c4];
    float4 bq = ((const float4*)(src + (p00 + 1) * NO))[c4];
    float4 c = ((const float4*)(src + (p00 + 64) * NO))[c4];
    float4 d = ((const float4*)(src + (p00 + 65) * NO))[c4];
    float4 r;
    r.x = fmaxf(fmaxf(a.x, bq.x), fmaxf(c.x, d.x));
    r.y = fmaxf(fmaxf(a.y, bq.y), fmaxf(c.y, d.y));
    r.z = fmaxf(fmaxf(a.z, bq.z), fmaxf(c.z, d.z));
    r.w = fmaxf(fmaxf(a.w, bq.w), fmaxf(c.w, d.w));
    ((float4*)dst)[idx] = r;
}

// ---------------- flash attention: per block 64 queries x 1024 keys ----------------
// thread grid 16x16: thread (ty,tx) owns S rows ty*4..+3, key cols tx+16j (j<4),
// O cols tx*4..+3 (half0) and 64+tx*4..+3 (half1).
__global__ void __launch_bounds__(256) attn_k(const float* __restrict__ G,
                                              const float* __restrict__ F,
                                              const float* __restrict__ H,
                                              float* __restrict__ O)
{
    __shared__ float Gs[64 * 36];
    __shared__ float FPs[64 * 68];   // F tile (cols 0..31) then P tile (cols 0..63)
    __shared__ float Hs[64 * 68];    // one 64-col half of H tile
    const int tid = threadIdx.x;
    const int tx = tid & 15, ty = tid >> 4;
    const int b  = blockIdx.x >> 6;
    const int q0 = (blockIdx.x & 63) * 64;
    const float* Gb = G + ((size_t)b * NB + q0) * 32;
    const float* Fb = F + (size_t)b * MB * 32;
    const float* Hb = H + (size_t)b * MB * 128;

    #pragma unroll
    for (int t = 0; t < 2; t++) {
        int idx = t * 256 + tid;
        int rr = idx >> 3, cc = (idx & 7) * 4;
        float4 v = *(const float4*)(Gb + (size_t)rr * 32 + cc);
        float* d = Gs + rr * 36 + cc;
        d[0] = v.x; d[1] = v.y; d[2] = v.z; d[3] = v.w;
    }

    float m[4], l[4];
    float4 oA[4], oB[4];
    #pragma unroll
    for (int i = 0; i < 4; i++) {
        m[i] = -1e30f; l[i] = 0.f;
        oA[i] = make_float4(0.f, 0.f, 0.f, 0.f);
        oB[i] = make_float4(0.f, 0.f, 0.f, 0.f);
    }

    for (int kt = 0; kt < 16; kt++) {
        const int k0 = kt * 64;
        __syncthreads();   // prior PV done before overwriting FPs/Hs
        // F tile -> FPs cols 0..31
        #pragma unroll
        for (int t = 0; t < 2; t++) {
            int idx = t * 256 + tid;
            int rr = idx >> 3, cc = (idx & 7) * 4;
            float4 v = *(const float4*)(Fb + (size_t)(k0 + rr) * 32 + cc);
            float* d = FPs + rr * 68 + cc;
            d[0] = v.x; d[1] = v.y; d[2] = v.z; d[3] = v.w;
        }
        // H tile half 0 (cols 0..63)
        #pragma unroll
        for (int t = 0; t < 4; t++) {
            int idx = t * 256 + tid;
            int rr = idx >> 4, cc = (idx & 15) * 4;
            float4 v = *(const float4*)(Hb + (size_t)(k0 + rr) * 128 + cc);
            float* d = Hs + rr * 68 + cc;
            d[0] = v.x; d[1] = v.y; d[2] = v.z; d[3] = v.w;
        }
        __syncthreads();

        // S = G @ F^T  (4x4 per thread, key col = tx + 16*j)
        float s[4][4];
        #pragma unroll
        for (int i = 0; i < 4; i++)
            #pragma unroll
            for (int j = 0; j < 4; j++) s[i][j] = 0.f;
        #pragma unroll
        for (int k = 0; k < 32; k += 4) {
            float4 gv[4], fv[4];
            #pragma unroll
            for (int i = 0; i < 4; i++)
                gv[i] = *(const float4*)(Gs + (ty * 4 + i) * 36 + k);
            #pragma unroll
            for (int j = 0; j < 4; j++)
                fv[j] = *(const float4*)(FPs + (tx + 16 * j) * 68 + k);
            #pragma unroll
            for (int i = 0; i < 4; i++)
                #pragma unroll
                for (int j = 0; j < 4; j++)
                    s[i][j] += gv[i].x * fv[j].x + gv[i].y * fv[j].y
                             + gv[i].z * fv[j].z + gv[i].w * fv[j].w;
        }

        // online softmax update
        #pragma unroll
        for (int i = 0; i < 4; i++) {
            float tm = fmaxf(fmaxf(s[i][0], s[i][1]), fmaxf(s[i][2], s[i][3]));
            #pragma unroll
            for (int off = 1; off < 16; off <<= 1)
                tm = fmaxf(tm, __shfl_xor_sync(0xffffffffu, tm, off));
            float mn = fmaxf(m[i], tm);
            float corr = __expf(m[i] - mn);
            m[i] = mn;
            float rs = 0.f;
            #pragma unroll
            for (int j = 0; j < 4; j++) { s[i][j] = __expf(s[i][j] - mn); rs += s[i][j]; }
            #pragma unroll
            for (int off = 1; off < 16; off <<= 1)
                rs += __shfl_xor_sync(0xffffffffu, rs, off);
            l[i] = l[i] * corr + rs;
            oA[i].x *= corr; oA[i].y *= corr; oA[i].z *= corr; oA[i].w *= corr;
            oB[i].x *= corr; oB[i].y *= corr; oB[i].z *= corr; oB[i].w *= corr;
        }
        __syncthreads();   // S reads of FPs done
        // store P
        #pragma unroll
        for (int i = 0; i < 4; i++)
            #pragma unroll
            for (int j = 0; j < 4; j++)
                FPs[(ty * 4 + i) * 68 + tx + 16 * j] = s[i][j];
        __syncthreads();

        // PV half 0
        #pragma unroll
        for (int k = 0; k < 64; k += 4) {
            float4 h0 = *(const float4*)(Hs + (k + 0) * 68 + tx * 4);
            float4 h1 = *(const float4*)(Hs + (k + 1) * 68 + tx * 4);
            float4 h2 = *(const float4*)(Hs + (k + 2) * 68 + tx * 4);
            float4 h3 = *(const float4*)(Hs + (k + 3) * 68 + tx * 4);
            #pragma unroll
            for (int i = 0; i < 4; i++) {
                float4 p = *(const float4*)(FPs + (ty * 4 + i) * 68 + k);
                oA[i].x += p.x * h0.x + p.y * h1.x + p.z * h2.x + p.w * h3.x;
                oA[i].y += p.x * h0.y + p.y * h1.y + p.z * h2.y + p.w * h3.y;
                oA[i].z += p.x * h0.z + p.y * h1.z + p.z * h2.z + p.w * h3.z;
                oA[i].w += p.x * h0.w + p.y * h1.w + p.z * h2.w + p.w * h3.w;
            }
        }
        __syncthreads();
        // H tile half 1 (cols 64..127)
        #pragma unroll
        for (int t = 0; t < 4; t++) {
            int idx = t * 256 + tid;
            int rr = idx >> 4, cc = (idx & 15) * 4;
            float4 v = *(const float4*)(Hb + (size_t)(k0 + rr) * 128 + 64 + cc);
            float* d = Hs + rr * 68 + cc;
            d[0] = v.x; d[1] = v.y; d[2] = v.z; d[3] = v.w;
        }
        __syncthreads();
        // PV half 1
        #pragma unroll
        for (int k = 0; k < 64; k += 4) {
            float4 h0 = *(const float4*)(Hs + (k + 0) * 68 + tx * 4);
            float4 h1 = *(const float4*)(Hs + (k + 1) * 68 + tx * 4);
            float4 h2 = *(const float4*)(Hs + (k + 2) * 68 + tx * 4);
            float4 h3 = *(const float4*)(Hs + (k + 3) * 68 + tx * 4);
            #pragma unroll
            for (int i = 0; i < 4; i++) {
                float4 p = *(const float4*)(FPs + (ty * 4 + i) * 68 + k);
                oB[i].x += p.x * h0.x + p.y * h1.x + p.z * h2.x + p.w * h3.x;
                oB[i].y += p.x * h0.y + p.y * h1.y + p.z * h2.y + p.w * h3.y;
                oB[i].z += p.x * h0.z + p.y * h1.z + p.z * h2.z + p.w * h3.z;
                oB[i].w += p.x * h0.w + p.y * h1.w + p.z * h2.w + p.w * h3.w;
            }
        }
    }

    // epilogue: normalize and store
    #pragma unroll
    for (int i = 0; i < 4; i++) {
        float inv = 1.f / l[i];
        float4 a = oA[i], c = oB[i];
        a.x *= inv; a.y *= inv; a.z *= inv; a.w *= inv;
        c.x *= inv; c.y *= inv; c.z *= inv; c.w *= inv;
        size_t row = (size_t)b * NB + q0 + ty * 4 + i;
        *(float4*)(O + row * 128 + tx * 4) = a;
        *(float4*)(O + row * 128 + 64 + tx * 4) = c;
    }
}

// ---------------- out = gamma * (o @ Wo + bo) + x ----------------
__global__ void __launch_bounds__(256) out_k(const float* __restrict__ Oin,
                                             const float* __restrict__ Wo,
                                             const float* __restrict__ bo,
                                             const float* __restrict__ x,
                                             const float* __restrict__ gamma,
                                             float* __restrict__ out)
{
    __shared__ float Os[32][33];
    __shared__ float Ws[32][260];
    const int tid  = threadIdx.x;
    const int row0 = blockIdx.x * 32;
    const int r    = tid & 31;
    const int c0   = (tid >> 5) * 32;
    float4 acc[8];
    #pragma unroll
    for (int j = 0; j < 8; j++) acc[j] = make_float4(0.f, 0.f, 0.f, 0.f);

    for (int kc = 0; kc < 128; kc += 32) {
        {
            int rr = tid >> 3, cc = (tid & 7) * 4;
            float4 v = *(const float4*)(Oin + (size_t)(row0 + rr) * 128 + kc + cc);
            Os[rr][cc] = v.x; Os[rr][cc+1] = v.y; Os[rr][cc+2] = v.z; Os[rr][cc+3] = v.w;
        }
        #pragma unroll
        for (int t = 0; t < 8; t++) {
            int idx = t * 256 + tid;
            int kk = idx >> 6, cc = (idx & 63) * 4;
            float4 v = *(const float4*)(Wo + (size_t)(kc + kk) * 256 + cc);
            Ws[kk][cc] = v.x; Ws[kk][cc+1] = v.y; Ws[kk][cc+2] = v.z; Ws[kk][cc+3] = v.w;
        }
        __syncthreads();
        #pragma unroll
        for (int k = 0; k < 32; k++) {
            float a = Os[r][k];
            #pragma unroll
            for (int j = 0; j < 8; j++) {
                float4 w = *(const float4*)(&Ws[k][c0 + 4 * j]);
                acc[j].x += a * w.x; acc[j].y += a * w.y;
                acc[j].z += a * w.z; acc[j].w += a * w.w;
            }
        }
        __syncthreads();
    }
    float gm = gamma[0];
    #pragma unroll
    for (int j = 0; j < 8; j++) {
        int c = c0 + 4 * j;
        float4 bb = *(const float4*)(bo + c);
        size_t off = (size_t)(row0 + r) * 256 + c;
        float4 xv = *(const float4*)(x + off);
        float4 v;
        v.x = gm * (acc[j].x + bb.x) + xv.x;
        v.y = gm * (acc[j].y + bb.y) + xv.y;
        v.z = gm * (acc[j].z + bb.z) + xv.z;
        v.w = gm * (acc[j].w + bb.w) + xv.w;
        *(float4*)(out + off) = v;
    }
}

// ---------------- launch ----------------
extern "C" void kernel_launch(void* const* d_in, const int* in_sizes, int n_in,
                              void* d_out, int out_size)
{
    (void)in_sizes; (void)n_in; (void)out_size;
    const float* x     = (const float*)d_in[0];
    const float* Wf    = (const float*)d_in[1];
    const float* bf    = (const float*)d_in[2];
    const float* Wg    = (const float*)d_in[3];
    const float* bg    = (const float*)d_in[4];
    const float* Wh    = (const float*)d_in[5];
    const float* bh    = (const float*)d_in[6];
    const float* Wo    = (const float*)d_in[7];
    const float* bo    = (const float*)d_in[8];
    const float* gamma = (const float*)d_in[9];
    float* out = (float*)d_out;

    float *pg, *pfpre, *phpre, *pf, *ph, *po;
    cudaGetSymbolAddress((void**)&pg,    g_g);
    cudaGetSymbolAddress((void**)&pfpre, g_fpre);
    cudaGetSymbolAddress((void**)&phpre, g_hpre);
    cudaGetSymbolAddress((void**)&pf,    g_f);
    cudaGetSymbolAddress((void**)&ph,    g_h);
    cudaGetSymbolAddress((void**)&po,    g_o);

    linear_k<32><<<NPIX / 64, 256>>>(x, Wg, bg, pg);
    linear_k<32><<<NPIX / 64, 256>>>(x, Wf, bf, pfpre);
    linear_k<128><<<NPIX / 64, 256>>>(x, Wh, bh, phpre);

    pool_k<32><<<(BATCH * MB * 8 + 255) / 256, 256>>>(pfpre, pf);
    pool_k<128><<<(BATCH * MB * 32 + 255) / 256, 256>>>(phpre, ph);

    attn_k<<<NPIX / 64, 256>>>(pg, pf, ph, po);

    out_k<<<NPIX / 32, 256>>>(po, Wo, bo, x, gamma, out);
}

// round 3
// speedup vs baseline: 1.3124x; 1.3106x over previous
#include <cuda_runtime.h>
#include <cstdint>

#define NB 4096      // pixels per batch (64*64)
#define MB 1024      // pooled pixels per batch (32*32)
#define BATCH 8
#define NPIX (BATCH*NB)   // 32768

// ---------------- scratch ----------------
__device__ float g_g[NPIX*32];
__device__ float g_fpre[NPIX*32];
__device__ float g_hpre[NPIX*128];
__device__ float g_f[BATCH*MB*32];
__device__ float g_h[BATCH*MB*128];
__device__ float g_o[NPIX*128];

// ---------------- fused projection: [g|f|h] = X @ [Wg|Wf|Wh] + b ----------------
// block: 128 rows x 192 cols. threads 256 (16 ty x 16 tx). thread tile 8 rows x 12 cols.
__global__ void __launch_bounds__(256) proj_k(const float* __restrict__ X,
    const float* __restrict__ Wg, const float* __restrict__ bg,
    const float* __restrict__ Wf, const float* __restrict__ bf,
    const float* __restrict__ Wh, const float* __restrict__ bh,
    float* __restrict__ Yg, float* __restrict__ Yf, float* __restrict__ Yh)
{
    __shared__ float Xs[128*36];
    __shared__ float Ws[32*200];
    const int tid = threadIdx.x, tx = tid & 15, ty = tid >> 4;
    const int row0 = blockIdx.x * 128;

    float4 acc[8][3];
    #pragma unroll
    for (int i = 0; i < 8; i++)
        #pragma unroll
        for (int g = 0; g < 3; g++) acc[i][g] = make_float4(0.f,0.f,0.f,0.f);

    for (int kc = 0; kc < 256; kc += 32) {
        #pragma unroll
        for (int t = 0; t < 4; t++) {
            int idx = t*256 + tid; int rr = idx >> 3, cc = (idx & 7) * 4;
            float4 v = *(const float4*)(X + (size_t)(row0+rr)*256 + kc + cc);
            float* d = Xs + rr*36 + cc;
            d[0]=v.x; d[1]=v.y; d[2]=v.z; d[3]=v.w;
        }
        #pragma unroll
        for (int t = 0; t < 6; t++) {
            int idx = t*256 + tid; int kk = idx / 48; int c = (idx % 48) * 4;
            float4 v;
            if (c < 32)       v = *(const float4*)(Wg + (size_t)(kc+kk)*32  + c);
            else if (c < 64)  v = *(const float4*)(Wf + (size_t)(kc+kk)*32  + (c-32));
            else              v = *(const float4*)(Wh + (size_t)(kc+kk)*128 + (c-64));
            float* d = Ws + kk*200 + c;
            d[0]=v.x; d[1]=v.y; d[2]=v.z; d[3]=v.w;
        }
        __syncthreads();
        #pragma unroll 4
        for (int k = 0; k < 32; k++) {
            float4 w0 = *(const float4*)(Ws + k*200 +       tx*4);
            float4 w1 = *(const float4*)(Ws + k*200 +  64 + tx*4);
            float4 w2 = *(const float4*)(Ws + k*200 + 128 + tx*4);
            #pragma unroll
            for (int i = 0; i < 8; i++) {
                float a = Xs[(ty*8+i)*36 + k];
                acc[i][0].x += a*w0.x; acc[i][0].y += a*w0.y; acc[i][0].z += a*w0.z; acc[i][0].w += a*w0.w;
                acc[i][1].x += a*w1.x; acc[i][1].y += a*w1.y; acc[i][1].z += a*w1.z; acc[i][1].w += a*w1.w;
                acc[i][2].x += a*w2.x; acc[i][2].y += a*w2.y; acc[i][2].z += a*w2.z; acc[i][2].w += a*w2.w;
            }
        }
        __syncthreads();
    }
    // epilogue
    #pragma unroll
    for (int i = 0; i < 8; i++) {
        size_t row = row0 + ty*8 + i;
        int c0 = tx * 4;
        float4 a = acc[i][0];
        if (tx < 8) {
            float4 bb = *(const float4*)(bg + c0);
            a.x+=bb.x; a.y+=bb.y; a.z+=bb.z; a.w+=bb.w;
            *(float4*)(Yg + row*32 + c0) = a;
        } else {
            float4 bb = *(const float4*)(bf + c0 - 32);
            a.x+=bb.x; a.y+=bb.y; a.z+=bb.z; a.w+=bb.w;
            *(float4*)(Yf + row*32 + c0 - 32) = a;
        }
        float4 b1 = *(const float4*)(bh + c0);
        float4 h1 = acc[i][1];
        h1.x+=b1.x; h1.y+=b1.y; h1.z+=b1.z; h1.w+=b1.w;
        *(float4*)(Yh + row*128 + c0) = h1;
        float4 b2 = *(const float4*)(bh + 64 + c0);
        float4 h2 = acc[i][2];
        h2.x+=b2.x; h2.y+=b2.y; h2.z+=b2.z; h2.w+=b2.w;
        *(float4*)(Yh + row*128 + 64 + c0) = h2;
    }
}

// ---------------- 2x2 maxpool ----------------
template<int NO>
__global__ void pool_k(const float* __restrict__ src, float* __restrict__ dst)
{
    int idx = blockIdx.x * blockDim.x + threadIdx.x;
    const int total = BATCH * MB * (NO / 4);
    if (idx >= total) return;
    int c4 = idx % (NO / 4);
    int m  = (idx / (NO / 4)) % MB;
    int b  = idx / ((NO / 4) * MB);
    int h2 = m >> 5, w2 = m & 31;
    size_t p00 = ((size_t)(b * 64 + h2 * 2) * 64 + w2 * 2);
    float4 a = ((const float4*)(src + p00 * NO))[c4];
    float4 bq = ((const float4*)(src + (p00 + 1) * NO))[c4];
    float4 c = ((const float4*)(src + (p00 + 64) * NO))[c4];
    float4 d = ((const float4*)(src + (p00 + 65) * NO))[c4];
    float4 r;
    r.x = fmaxf(fmaxf(a.x, bq.x), fmaxf(c.x, d.x));
    r.y = fmaxf(fmaxf(a.y, bq.y), fmaxf(c.y, d.y));
    r.z = fmaxf(fmaxf(a.z, bq.z), fmaxf(c.z, d.z));
    r.w = fmaxf(fmaxf(a.w, bq.w), fmaxf(c.w, d.w));
    ((float4*)dst)[idx] = r;
}

// ---------------- flash attention: 128 queries/block, 16 key-tiles of 64 ----------------
// thread grid 16x16. Thread (ty,tx): S rows ty*8..+7, keys tx*4..+3,
// O cols {tx*4..+3, 64+tx*4..+3}.
// smem layout (floats): Gs[128][36] @0, Fs[32][68] @4608 (F transposed [k][key]),
// Hs[64][132] @6784, Ps[128][68] @15232.  total 23936 floats = 95744 B.
#define ATTN_SMEM_BYTES 95744

__global__ void __launch_bounds__(256) attn_k(const float* __restrict__ G,
                                              const float* __restrict__ F,
                                              const float* __restrict__ H,
                                              float* __restrict__ O)
{
    extern __shared__ float sm[];
    float* Gs = sm;            // [128][36]
    float* Fs = sm + 4608;     // [32][68]
    float* Hs = sm + 6784;     // [64][132]
    float* Ps = sm + 15232;    // [128][68]

    const int tid = threadIdx.x, tx = tid & 15, ty = tid >> 4;
    const int b  = blockIdx.x >> 5;
    const int q0 = (blockIdx.x & 31) * 128;
    const float* Gb = G + ((size_t)b * NB + q0) * 32;
    const float* Fb = F + (size_t)b * MB * 32;
    const float* Hb = H + (size_t)b * MB * 128;

    #pragma unroll
    for (int t = 0; t < 4; t++) {
        int idx = t*256 + tid; int rr = idx >> 3, cc = (idx & 7) * 4;
        float4 v = *(const float4*)(Gb + (size_t)rr*32 + cc);
        float* d = Gs + rr*36 + cc;
        d[0]=v.x; d[1]=v.y; d[2]=v.z; d[3]=v.w;
    }

    float m[8], l[8];
    float4 oA[8], oB[8];
    #pragma unroll
    for (int i = 0; i < 8; i++) {
        m[i] = -1e30f; l[i] = 0.f;
        oA[i] = make_float4(0.f,0.f,0.f,0.f);
        oB[i] = make_float4(0.f,0.f,0.f,0.f);
    }

    #pragma unroll 1
    for (int kt = 0; kt < 16; kt++) {
        const int k0 = kt * 64;
        __syncthreads();   // previous PV reads of Hs/Ps done
        // F tile transposed -> Fs[k][key]
        #pragma unroll
        for (int t = 0; t < 2; t++) {
            int idx = t*256 + tid; int key = idx >> 3, kk = (idx & 7) * 4;
            float4 v = *(const float4*)(Fb + (size_t)(k0+key)*32 + kk);
            Fs[(kk+0)*68 + key] = v.x;
            Fs[(kk+1)*68 + key] = v.y;
            Fs[(kk+2)*68 + key] = v.z;
            Fs[(kk+3)*68 + key] = v.w;
        }
        // H tile -> Hs[k][col]
        #pragma unroll
        for (int t = 0; t < 8; t++) {
            int idx = t*256 + tid; int k = idx >> 5, cc = (idx & 31) * 4;
            float4 v = *(const float4*)(Hb + (size_t)(k0+k)*128 + cc);
            float* d = Hs + k*132 + cc;
            d[0]=v.x; d[1]=v.y; d[2]=v.z; d[3]=v.w;
        }
        __syncthreads();

        // ---- S = G @ F^T : per-thread 8 rows x 4 keys ----
        float s[8][4];
        #pragma unroll
        for (int i = 0; i < 8; i++)
            #pragma unroll
            for (int j = 0; j < 4; j++) s[i][j] = 0.f;
        #pragma unroll 2
        for (int kc = 0; kc < 32; kc += 4) {
            float4 fv0 = *(const float4*)(Fs + (kc+0)*68 + tx*4);
            float4 fv1 = *(const float4*)(Fs + (kc+1)*68 + tx*4);
            float4 fv2 = *(const float4*)(Fs + (kc+2)*68 + tx*4);
            float4 fv3 = *(const float4*)(Fs + (kc+3)*68 + tx*4);
            #pragma unroll
            for (int i = 0; i < 8; i++) {
                float4 g = *(const float4*)(Gs + (ty*8+i)*36 + kc);
                s[i][0] += g.x*fv0.x + g.y*fv1.x + g.z*fv2.x + g.w*fv3.x;
                s[i][1] += g.x*fv0.y + g.y*fv1.y + g.z*fv2.y + g.w*fv3.y;
                s[i][2] += g.x*fv0.z + g.y*fv1.z + g.z*fv2.z + g.w*fv3.z;
                s[i][3] += g.x*fv0.w + g.y*fv1.w + g.z*fv2.w + g.w*fv3.w;
            }
        }

        // ---- online softmax ----
        #pragma unroll
        for (int i = 0; i < 8; i++) {
            float tm = fmaxf(fmaxf(s[i][0], s[i][1]), fmaxf(s[i][2], s[i][3]));
            #pragma unroll
            for (int off = 1; off < 16; off <<= 1)
                tm = fmaxf(tm, __shfl_xor_sync(0xffffffffu, tm, off));
            float mn = fmaxf(m[i], tm);
            float corr = __expf(m[i] - mn);
            m[i] = mn;
            float rs = 0.f;
            #pragma unroll
            for (int j = 0; j < 4; j++) { s[i][j] = __expf(s[i][j] - mn); rs += s[i][j]; }
            #pragma unroll
            for (int off = 1; off < 16; off <<= 1)
                rs += __shfl_xor_sync(0xffffffffu, rs, off);
            l[i] = l[i] * corr + rs;
            oA[i].x *= corr; oA[i].y *= corr; oA[i].z *= corr; oA[i].w *= corr;
            oB[i].x *= corr; oB[i].y *= corr; oB[i].z *= corr; oB[i].w *= corr;
        }

        // ---- store P ----
        #pragma unroll
        for (int i = 0; i < 8; i++)
            *(float4*)(Ps + (ty*8+i)*68 + tx*4) = make_float4(s[i][0], s[i][1], s[i][2], s[i][3]);
        __syncthreads();

        // ---- PV: per-thread 8 rows x 8 cols ----
        #pragma unroll 2
        for (int k = 0; k < 64; k += 4) {
            float4 a0 = *(const float4*)(Hs + (k+0)*132 + tx*4);
            float4 a1 = *(const float4*)(Hs + (k+1)*132 + tx*4);
            float4 a2 = *(const float4*)(Hs + (k+2)*132 + tx*4);
            float4 a3 = *(const float4*)(Hs + (k+3)*132 + tx*4);
            float4 b0 = *(const float4*)(Hs + (k+0)*132 + 64 + tx*4);
            float4 b1 = *(const float4*)(Hs + (k+1)*132 + 64 + tx*4);
            float4 b2 = *(const float4*)(Hs + (k+2)*132 + 64 + tx*4);
            float4 b3 = *(const float4*)(Hs + (k+3)*132 + 64 + tx*4);
            #pragma unroll
            for (int i = 0; i < 8; i++) {
                float4 p = *(const float4*)(Ps + (ty*8+i)*68 + k);
                oA[i].x += p.x*a0.x + p.y*a1.x + p.z*a2.x + p.w*a3.x;
                oA[i].y += p.x*a0.y + p.y*a1.y + p.z*a2.y + p.w*a3.y;
                oA[i].z += p.x*a0.z + p.y*a1.z + p.z*a2.z + p.w*a3.z;
                oA[i].w += p.x*a0.w + p.y*a1.w + p.z*a2.w + p.w*a3.w;
                oB[i].x += p.x*b0.x + p.y*b1.x + p.z*b2.x + p.w*b3.x;
                oB[i].y += p.x*b0.y + p.y*b1.y + p.z*b2.y + p.w*b3.y;
                oB[i].z += p.x*b0.z + p.y*b1.z + p.z*b2.z + p.w*b3.z;
                oB[i].w += p.x*b0.w + p.y*b1.w + p.z*b2.w + p.w*b3.w;
            }
        }
    }

    // ---- epilogue ----
    #pragma unroll
    for (int i = 0; i < 8; i++) {
        float inv = 1.f / l[i];
        float4 a = oA[i], c = oB[i];
        a.x*=inv; a.y*=inv; a.z*=inv; a.w*=inv;
        c.x*=inv; c.y*=inv; c.z*=inv; c.w*=inv;
        size_t row = (size_t)b * NB + q0 + ty*8 + i;
        *(float4*)(O + row*128 + tx*4) = a;
        *(float4*)(O + row*128 + 64 + tx*4) = c;
    }
}

// ---------------- out = gamma * (o @ Wo + bo) + x ----------------
// block: 128 rows x 256 cols. thread tile 8 rows x 16 cols. K chunks of 16.
__global__ void __launch_bounds__(256) out_k(const float* __restrict__ Oin,
                                             const float* __restrict__ Wo,
                                             const float* __restrict__ bo,
                                             const float* __restrict__ x,
                                             const float* __restrict__ gamma,
                                             float* __restrict__ out)
{
    __shared__ float Os[128*20];
    __shared__ float Ws2[16*260];
    const int tid = threadIdx.x, tx = tid & 15, ty = tid >> 4;
    const int row0 = blockIdx.x * 128;

    float4 acc[8][4];
    #pragma unroll
    for (int i = 0; i < 8; i++)
        #pragma unroll
        for (int g = 0; g < 4; g++) acc[i][g] = make_float4(0.f,0.f,0.f,0.f);

    for (int kc = 0; kc < 128; kc += 16) {
        #pragma unroll
        for (int t = 0; t < 2; t++) {
            int idx = t*256 + tid; int rr = idx >> 2, cc = (idx & 3) * 4;
            float4 v = *(const float4*)(Oin + (size_t)(row0+rr)*128 + kc + cc);
            float* d = Os + rr*20 + cc;
            d[0]=v.x; d[1]=v.y; d[2]=v.z; d[3]=v.w;
        }
        #pragma unroll
        for (int t = 0; t < 4; t++) {
            int idx = t*256 + tid; int kk = idx >> 6, cc = (idx & 63) * 4;
            float4 v = *(const float4*)(Wo + (size_t)(kc+kk)*256 + cc);
            float* d = Ws2 + kk*260 + cc;
            d[0]=v.x; d[1]=v.y; d[2]=v.z; d[3]=v.w;
        }
        __syncthreads();
        #pragma unroll 4
        for (int k = 0; k < 16; k++) {
            float4 w0 = *(const float4*)(Ws2 + k*260 +       tx*4);
            float4 w1 = *(const float4*)(Ws2 + k*260 +  64 + tx*4);
            float4 w2 = *(const float4*)(Ws2 + k*260 + 128 + tx*4);
            float4 w3 = *(const float4*)(Ws2 + k*260 + 192 + tx*4);
            #pragma unroll
            for (int i = 0; i < 8; i++) {
                float a = Os[(ty*8+i)*20 + k];
                acc[i][0].x += a*w0.x; acc[i][0].y += a*w0.y; acc[i][0].z += a*w0.z; acc[i][0].w += a*w0.w;
                acc[i][1].x += a*w1.x; acc[i][1].y += a*w1.y; acc[i][1].z += a*w1.z; acc[i][1].w += a*w1.w;
                acc[i][2].x += a*w2.x; acc[i][2].y += a*w2.y; acc[i][2].z += a*w2.z; acc[i][2].w += a*w2.w;
                acc[i][3].x += a*w3.x; acc[i][3].y += a*w3.y; acc[i][3].z += a*w3.z; acc[i][3].w += a*w3.w;
            }
        }
        __syncthreads();
    }
    float gm = gamma[0];
    #pragma unroll
    for (int i = 0; i < 8; i++) {
        size_t row = row0 + ty*8 + i;
        #pragma unroll
        for (int g = 0; g < 4; g++) {
            int c = g*64 + tx*4;
            float4 bb = *(const float4*)(bo + c);
            size_t off = row*256 + c;
            float4 xv = *(const float4*)(x + off);
            float4 v;
            v.x = gm * (acc[i][g].x + bb.x) + xv.x;
            v.y = gm * (acc[i][g].y + bb.y) + xv.y;
            v.z = gm * (acc[i][g].z + bb.z) + xv.z;
            v.w = gm * (acc[i][g].w + bb.w) + xv.w;
            *(float4*)(out + off) = v;
        }
    }
}

// ---------------- launch ----------------
extern "C" void kernel_launch(void* const* d_in, const int* in_sizes, int n_in,
                              void* d_out, int out_size)
{
    (void)in_sizes; (void)n_in; (void)out_size;
    const float* x     = (const float*)d_in[0];
    const float* Wf    = (const float*)d_in[1];
    const float* bf    = (const float*)d_in[2];
    const float* Wg    = (const float*)d_in[3];
    const float* bg    = (const float*)d_in[4];
    const float* Wh    = (const float*)d_in[5];
    const float* bh    = (const float*)d_in[6];
    const float* Wo    = (const float*)d_in[7];
    const float* bo    = (const float*)d_in[8];
    const float* gamma = (const float*)d_in[9];
    float* out = (float*)d_out;

    float *pg, *pfpre, *phpre, *pf, *ph, *po;
    cudaGetSymbolAddress((void**)&pg,    g_g);
    cudaGetSymbolAddress((void**)&pfpre, g_fpre);
    cudaGetSymbolAddress((void**)&phpre, g_hpre);
    cudaGetSymbolAddress((void**)&pf,    g_f);
    cudaGetSymbolAddress((void**)&ph,    g_h);
    cudaGetSymbolAddress((void**)&po,    g_o);

    static bool attr_set = false;
    if (!attr_set) {
        cudaFuncSetAttribute(attn_k, cudaFuncAttributeMaxDynamicSharedMemorySize,
                             ATTN_SMEM_BYTES);
        attr_set = true;
    }

    proj_k<<<NPIX / 128, 256>>>(x, Wg, bg, Wf, bf, Wh, bh, pg, pfpre, phpre);

    pool_k<32><<<(BATCH * MB * 8 + 255) / 256, 256>>>(pfpre, pf);
    pool_k<128><<<(BATCH * MB * 32 + 255) / 256, 256>>>(phpre, ph);

    attn_k<<<NPIX / 128, 256, ATTN_SMEM_BYTES>>>(pg, pf, ph, po);

    out_k<<<NPIX / 128, 256>>>(po, Wo, bo, x, gamma, out);
}

// round 6
// speedup vs baseline: 5.0919x; 3.8797x over previous
#include <cuda_runtime.h>
#include <cuda_bf16.h>
#include <cstdint>

#define NB 4096
#define MB 1024
#define BATCH 8
#define NPIX (BATCH*NB)   // 32768

// ---------------- scratch (bf16) ----------------
__device__ __nv_bfloat16 g_wt[192*256];            // [n][k] transposed Wg|Wf|Wh
__device__ __nv_bfloat16 g_wot[256*128];           // [n][k] transposed Wo
__device__ __nv_bfloat16 g_gb[(size_t)NPIX*32];    // g [row][32]
__device__ __nv_bfloat16 g_fpre[(size_t)NPIX*32];  // f pre-pool [row][32]
__device__ __nv_bfloat16 g_fp[BATCH*MB*32];        // f pooled [b*M][32]
__device__ __nv_bfloat16 g_hpt[(size_t)BATCH*128*NB]; // h pre-pool TRANSPOSED [b][c][n]
__device__ __nv_bfloat16 g_ht[BATCH*128*MB];       // h pooled TRANSPOSED [b][c][m]
__device__ __nv_bfloat16 g_obf[(size_t)NPIX*128];  // attention out [row][128]

// ---------------- helpers ----------------
__device__ __forceinline__ uint32_t packbf(float lo, float hi) {
    __nv_bfloat162 h = __float22bfloat162_rn(make_float2(lo, hi));
    return *reinterpret_cast<uint32_t*>(&h);
}
__device__ __forceinline__ void mma_bf16(float* c,
    uint32_t a0, uint32_t a1, uint32_t a2, uint32_t a3,
    uint32_t b0, uint32_t b1)
{
    asm volatile(
        "mma.sync.aligned.m16n8k16.row.col.f32.bf16.bf16.f32 "
        "{%0,%1,%2,%3},{%4,%5,%6,%7},{%8,%9},{%0,%1,%2,%3};\n"
        : "+f"(c[0]), "+f"(c[1]), "+f"(c[2]), "+f"(c[3])
        : "r"(a0), "r"(a1), "r"(a2), "r"(a3), "r"(b0), "r"(b1));
}
__device__ __forceinline__ void ldm4(uint32_t& r0, uint32_t& r1, uint32_t& r2, uint32_t& r3,
                                     uint32_t addr)
{
    asm volatile("ldmatrix.sync.aligned.m8n8.x4.shared.b16 {%0,%1,%2,%3}, [%4];\n"
                 : "=r"(r0), "=r"(r1), "=r"(r2), "=r"(r3) : "r"(addr));
}

// ---------------- prep: transpose + convert weights ----------------
__global__ void prep_k(const float* __restrict__ Wf, const float* __restrict__ Wg,
                       const float* __restrict__ Wh, const float* __restrict__ Wo)
{
    int idx = blockIdx.x * 256 + threadIdx.x;     // 192 blocks -> 49152
    if (idx < 192*256) {
        int n = idx >> 8, k = idx & 255;
        float v = (n < 32) ? Wg[k*32 + n] : (n < 64) ? Wf[k*32 + (n-32)] : Wh[k*128 + (n-64)];
        g_wt[idx] = __float2bfloat16(v);
    }
    if (idx < 256*128) {
        int n = idx >> 7, k = idx & 127;
        g_wot[idx] = __float2bfloat16(Wo[k*256 + n]);
    }
}

// ---------------- projection: [g|f|h] = X @ Wt^T, mma bf16 ----------------
// block 128 rows x 192 cols; 8 warps x 16-row stripes; 24 n-tiles per warp.
__global__ void __launch_bounds__(256) proj_k(const float* __restrict__ X,
    const float* __restrict__ bg, const float* __restrict__ bfv, const float* __restrict__ bh)
{
    __shared__ uint32_t Xs[128*20];   // bf16 [128][40]
    __shared__ uint32_t Ws[192*20];   // bf16 [192][40]
    const int tid = threadIdx.x, lane = tid & 31, w = tid >> 5;
    const int gp = lane >> 2, tg = lane & 3, l8 = lane & 7, gq = lane >> 3;
    const int row0 = blockIdx.x * 128;

    float acc[24][4];
    #pragma unroll
    for (int j = 0; j < 24; j++)
        #pragma unroll
        for (int i = 0; i < 4; i++) acc[j][i] = 0.f;

    const uint32_t sX = (uint32_t)__cvta_generic_to_shared(Xs);
    const uint32_t sW = (uint32_t)__cvta_generic_to_shared(Ws);
    const uint32_t aOff = sX + ((16*w + l8 + 8*(gq&1))*40 + 8*(gq>>1))*2;
    const uint32_t bRowOff = (l8 + 8*(gq>>1))*40 + 8*(gq&1);

    for (int kc = 0; kc < 256; kc += 32) {
        __syncthreads();
        #pragma unroll
        for (int t = 0; t < 4; t++) {
            int idx = t*256 + tid; int rr = idx >> 3, q = idx & 7;
            float4 v = *(const float4*)(X + (size_t)(row0+rr)*256 + kc + q*4);
            Xs[rr*20 + q*2]     = packbf(v.x, v.y);
            Xs[rr*20 + q*2 + 1] = packbf(v.z, v.w);
        }
        const uint4* wsrc = (const uint4*)g_wt;
        #pragma unroll
        for (int t = 0; t < 3; t++) {
            int idx = t*256 + tid; int rr = idx >> 2, q = idx & 3;
            uint4 v = wsrc[(size_t)rr*32 + (kc>>3) + q];
            *(uint4*)&Ws[rr*20 + q*4] = v;
        }
        __syncthreads();
        #pragma unroll
        for (int ks = 0; ks < 2; ks++) {
            uint32_t a0,a1,a2,a3;
            ldm4(a0,a1,a2,a3, aOff + ks*32);
            #pragma unroll
            for (int jp = 0; jp < 12; jp++) {
                uint32_t b0,b1,b2,b3;
                ldm4(b0,b1,b2,b3, sW + (16*jp*40 + bRowOff + ks*16)*2);
                mma_bf16(acc[2*jp],   a0,a1,a2,a3, b0,b1);
                mma_bf16(acc[2*jp+1], a0,a1,a2,a3, b2,b3);
            }
        }
    }

    // epilogue
    const int r0g = row0 + 16*w + gp, r1g = r0g + 8;
    const int bz = r0g >> 12;
    uint32_t* gout = (uint32_t*)g_gb;
    uint32_t* fout = (uint32_t*)g_fpre;
    #pragma unroll
    for (int j = 0; j < 24; j++) {
        int nb = 8*j, cp = nb + 2*tg;
        if (nb < 32) {
            float b0v = bg[cp], b1v = bg[cp+1];
            gout[(size_t)r0g*16 + (cp>>1)] = packbf(acc[j][0]+b0v, acc[j][1]+b1v);
            gout[(size_t)r1g*16 + (cp>>1)] = packbf(acc[j][2]+b0v, acc[j][3]+b1v);
        } else if (nb < 64) {
            int c = cp - 32;
            float b0v = bfv[c], b1v = bfv[c+1];
            fout[(size_t)r0g*16 + (c>>1)] = packbf(acc[j][0]+b0v, acc[j][1]+b1v);
            fout[(size_t)r1g*16 + (c>>1)] = packbf(acc[j][2]+b0v, acc[j][3]+b1v);
        } else {
            int c = cp - 64;
            float b0v = bh[c], b1v = bh[c+1];
            size_t base0 = ((size_t)(bz*128 + c))*4096;
            size_t base1 = base0 + 4096;
            int n0l = r0g & 4095, n1l = r1g & 4095;
            g_hpt[base0 + n0l] = __float2bfloat16(acc[j][0] + b0v);
            g_hpt[base1 + n0l] = __float2bfloat16(acc[j][1] + b1v);
            g_hpt[base0 + n1l] = __float2bfloat16(acc[j][2] + b0v);
            g_hpt[base1 + n1l] = __float2bfloat16(acc[j][3] + b1v);
        }
    }
}

// ---------------- pool f: [b*N][32] -> [b*M][32] ----------------
__global__ void pool_f_k()
{
    int idx = blockIdx.x * 256 + threadIdx.x;   // 131072
    int c2 = idx & 15, m = (idx >> 4) & 1023, b = idx >> 14;
    int h2 = m >> 5, w2 = m & 31;
    size_t r00 = (size_t)b*4096 + h2*128 + w2*2;
    const uint32_t* fp = (const uint32_t*)g_fpre;
    uint32_t u00 = fp[r00*16 + c2];
    uint32_t u01 = fp[(r00+1)*16 + c2];
    uint32_t u10 = fp[(r00+64)*16 + c2];
    uint32_t u11 = fp[(r00+65)*16 + c2];
    __nv_bfloat162 v = __hmax2(__hmax2(*(__nv_bfloat162*)&u00, *(__nv_bfloat162*)&u01),
                               __hmax2(*(__nv_bfloat162*)&u10, *(__nv_bfloat162*)&u11));
    ((uint32_t*)g_fp)[idx] = *(uint32_t*)&v;
}

// ---------------- pool h (transposed layout): [b][c][n] -> [b][c][m] ----------------
__global__ void pool_h_k()
{
    int idx = blockIdx.x * 256 + threadIdx.x;   // 524288
    int m2 = idx & 511, cc = (idx >> 9) & 127, b = idx >> 16;
    const uint32_t* src = (const uint32_t*)g_hpt + ((size_t)(b*128 + cc))*2048;
    int m = m2*2;
    int h2 = m >> 5, w2a = m & 31;
    int base = h2*64 + w2a;
    uint2 ua = *(const uint2*)(src + base);
    uint2 ub = *(const uint2*)(src + base + 32);
    __nv_bfloat162 va = __hmax2(*(__nv_bfloat162*)&ua.x, *(__nv_bfloat162*)&ub.x);
    __nv_bfloat162 vb = __hmax2(*(__nv_bfloat162*)&ua.y, *(__nv_bfloat162*)&ub.y);
    __nv_bfloat16 r0 = __hmax(__low2bfloat16(va), __high2bfloat16(va));
    __nv_bfloat16 r1 = __hmax(__low2bfloat16(vb), __high2bfloat16(vb));
    __nv_bfloat162 rp = __halves2bfloat162(r0, r1);
    ((uint32_t*)g_ht)[((size_t)(b*128 + cc))*512 + m2] = *(uint32_t*)&rp;
}

// ---------------- flash attention, bf16 mma ----------------
// block = 128 queries x 1024 keys (16 tiles of 64). 8 warps x 16-row stripes.
__global__ void __launch_bounds__(256) attn_k()
{
    __shared__ uint32_t Gs[128*20];   // bf16 [128][40]
    __shared__ uint32_t Fs[64*20];    // bf16 [64][40]
    __shared__ uint32_t Hs[128*36];   // bf16 [128 cols][72 keys]
    const int tid = threadIdx.x, lane = tid & 31, w = tid >> 5;
    const int gp = lane >> 2, tg = lane & 3, l8 = lane & 7, gq = lane >> 3;
    const int b = blockIdx.x >> 5, q0 = (blockIdx.x & 31)*128;

    const uint32_t* gsrc = (const uint32_t*)g_gb + ((size_t)b*NB + q0)*16;
    #pragma unroll
    for (int t = 0; t < 8; t++) {
        int idx = t*256 + tid; int rr = idx >> 4, q = idx & 15;
        Gs[rr*20 + q] = gsrc[(size_t)rr*16 + q];
    }

    const uint32_t sG = (uint32_t)__cvta_generic_to_shared(Gs);
    const uint32_t sF = (uint32_t)__cvta_generic_to_shared(Fs);
    const uint32_t sH = (uint32_t)__cvta_generic_to_shared(Hs);
    const uint32_t aOff = sG + ((16*w + l8 + 8*(gq&1))*40 + 8*(gq>>1))*2;
    const uint32_t bRow40 = (l8 + 8*(gq>>1))*40 + 8*(gq&1);
    const uint32_t bRow72 = (l8 + 8*(gq>>1))*72 + 8*(gq&1);

    float m0v = -1e30f, m1v = -1e30f, l0v = 0.f, l1v = 0.f;
    float o[16][4];
    #pragma unroll
    for (int j = 0; j < 16; j++)
        #pragma unroll
        for (int i = 0; i < 4; i++) o[j][i] = 0.f;

    #pragma unroll 1
    for (int kt = 0; kt < 16; kt++) {
        const int k0 = kt*64;
        __syncthreads();
        const uint32_t* fsrc = (const uint32_t*)g_fp + ((size_t)b*MB + k0)*16;
        #pragma unroll
        for (int t = 0; t < 4; t++) {
            int idx = t*256 + tid; int rr = idx >> 4, q = idx & 15;
            Fs[rr*20 + q] = fsrc[(size_t)rr*16 + q];
        }
        const uint32_t* hsrc = (const uint32_t*)g_ht + (size_t)b*128*512 + (k0 >> 1);
        #pragma unroll
        for (int t = 0; t < 16; t++) {            // FIX (was t < 8): fill ALL 128 channel rows
            int idx = t*256 + tid; int rr = idx >> 5, q = idx & 31;
            Hs[rr*36 + q] = hsrc[(size_t)rr*512 + q];
        }
        __syncthreads();

        // S = G @ F^T
        float s[8][4];
        #pragma unroll
        for (int j = 0; j < 8; j++)
            #pragma unroll
            for (int i = 0; i < 4; i++) s[j][i] = 0.f;
        #pragma unroll
        for (int ks = 0; ks < 2; ks++) {
            uint32_t a0,a1,a2,a3;
            ldm4(a0,a1,a2,a3, aOff + ks*32);
            #pragma unroll
            for (int jp = 0; jp < 4; jp++) {
                uint32_t b0,b1,b2,b3;
                ldm4(b0,b1,b2,b3, sF + (16*jp*40 + bRow40 + ks*16)*2);
                mma_bf16(s[2*jp],   a0,a1,a2,a3, b0,b1);
                mma_bf16(s[2*jp+1], a0,a1,a2,a3, b2,b3);
            }
        }

        // online softmax: row0 = gp (s[j][0..1]), row1 = gp+8 (s[j][2..3])
        {
            float tm = -1e30f;
            #pragma unroll
            for (int j = 0; j < 8; j++) tm = fmaxf(tm, fmaxf(s[j][0], s[j][1]));
            tm = fmaxf(tm, __shfl_xor_sync(0xffffffffu, tm, 1));
            tm = fmaxf(tm, __shfl_xor_sync(0xffffffffu, tm, 2));
            float mn = fmaxf(m0v, tm);
            float corr = __expf(m0v - mn);
            m0v = mn;
            float rs = 0.f;
            #pragma unroll
            for (int j = 0; j < 8; j++) {
                s[j][0] = __expf(s[j][0] - mn);
                s[j][1] = __expf(s[j][1] - mn);
                rs += s[j][0] + s[j][1];
            }
            rs += __shfl_xor_sync(0xffffffffu, rs, 1);
            rs += __shfl_xor_sync(0xffffffffu, rs, 2);
            l0v = l0v * corr + rs;
            #pragma unroll
            for (int j = 0; j < 16; j++) { o[j][0] *= corr; o[j][1] *= corr; }
        }
        {
            float tm = -1e30f;
            #pragma unroll
            for (int j = 0; j < 8; j++) tm = fmaxf(tm, fmaxf(s[j][2], s[j][3]));
            tm = fmaxf(tm, __shfl_xor_sync(0xffffffffu, tm, 1));
            tm = fmaxf(tm, __shfl_xor_sync(0xffffffffu, tm, 2));
            float mn = fmaxf(m1v, tm);
            float corr = __expf(m1v - mn);
            m1v = mn;
            float rs = 0.f;
            #pragma unroll
            for (int j = 0; j < 8; j++) {
                s[j][2] = __expf(s[j][2] - mn);
                s[j][3] = __expf(s[j][3] - mn);
                rs += s[j][2] + s[j][3];
            }
            rs += __shfl_xor_sync(0xffffffffu, rs, 1);
            rs += __shfl_xor_sync(0xffffffffu, rs, 2);
            l1v = l1v * corr + rs;
            #pragma unroll
            for (int j = 0; j < 16; j++) { o[j][2] *= corr; o[j][3] *= corr; }
        }

        // P -> bf16 A fragments (register-direct)
        uint32_t pa[4][4];
        #pragma unroll
        for (int ks = 0; ks < 4; ks++) {
            pa[ks][0] = packbf(s[2*ks][0],   s[2*ks][1]);
            pa[ks][1] = packbf(s[2*ks][2],   s[2*ks][3]);
            pa[ks][2] = packbf(s[2*ks+1][0], s[2*ks+1][1]);
            pa[ks][3] = packbf(s[2*ks+1][2], s[2*ks+1][3]);
        }

        // O += P @ H   (B from transposed-H smem)
        #pragma unroll
        for (int jp = 0; jp < 8; jp++) {
            #pragma unroll
            for (int ks = 0; ks < 4; ks++) {
                uint32_t b0,b1,b2,b3;
                ldm4(b0,b1,b2,b3, sH + (16*jp*72 + bRow72 + ks*16)*2);
                mma_bf16(o[2*jp],   pa[ks][0],pa[ks][1],pa[ks][2],pa[ks][3], b0,b1);
                mma_bf16(o[2*jp+1], pa[ks][0],pa[ks][1],pa[ks][2],pa[ks][3], b2,b3);
            }
        }
    }

    // epilogue: normalize, store bf16
    const float inv0 = 1.f / l0v, inv1 = 1.f / l1v;
    uint32_t* osink = (uint32_t*)g_obf;
    const int r0g = b*NB + q0 + 16*w + gp, r1g = r0g + 8;
    #pragma unroll
    for (int j = 0; j < 16; j++) {
        osink[(size_t)r0g*64 + 4*j + tg] = packbf(o[j][0]*inv0, o[j][1]*inv0);
        osink[(size_t)r1g*64 + 4*j + tg] = packbf(o[j][2]*inv1, o[j][3]*inv1);
    }
}

// ---------------- out = gamma * (O @ Wo + bo) + x ----------------
// block 128 rows x 128 cols; grid (rows/128)*2
__global__ void __launch_bounds__(256) out_k(const float* __restrict__ x,
    const float* __restrict__ bo, const float* __restrict__ gamma,
    float* __restrict__ out)
{
    __shared__ uint32_t Os[128*36];   // bf16 [128][72]
    __shared__ uint32_t Wos[128*36];
    const int tid = threadIdx.x, lane = tid & 31, w = tid >> 5;
    const int gp = lane >> 2, tg = lane & 3, l8 = lane & 7, gq = lane >> 3;
    const int row0 = (blockIdx.x >> 1)*128, col0 = (blockIdx.x & 1)*128;

    float acc[16][4];
    #pragma unroll
    for (int j = 0; j < 16; j++)
        #pragma unroll
        for (int i = 0; i < 4; i++) acc[j][i] = 0.f;

    const uint32_t sO = (uint32_t)__cvta_generic_to_shared(Os);
    const uint32_t sW = (uint32_t)__cvta_generic_to_shared(Wos);
    const uint32_t aRowOff = (16*w + l8 + 8*(gq&1))*72 + 8*(gq>>1);
    const uint32_t bRowOff = (l8 + 8*(gq>>1))*72 + 8*(gq&1);

    for (int kc = 0; kc < 128; kc += 64) {
        __syncthreads();
        const uint32_t* osrc = (const uint32_t*)g_obf + (kc >> 1);
        #pragma unroll
        for (int t = 0; t < 16; t++) {
            int idx = t*256 + tid; int rr = idx >> 5, q = idx & 31;
            Os[rr*36 + q] = osrc[(size_t)(row0+rr)*64 + q];
        }
        const uint32_t* wsrc = (const uint32_t*)g_wot + (kc >> 1);
        #pragma unroll
        for (int t = 0; t < 16; t++) {
            int idx = t*256 + tid; int rr = idx >> 5, q = idx & 31;
            Wos[rr*36 + q] = wsrc[(size_t)(col0+rr)*64 + q];
        }
        __syncthreads();
        #pragma unroll
        for (int ks = 0; ks < 4; ks++) {
            uint32_t a0,a1,a2,a3;
            ldm4(a0,a1,a2,a3, sO + (aRowOff + ks*16)*2);
            #pragma unroll
            for (int jp = 0; jp < 8; jp++) {
                uint32_t b0,b1,b2,b3;
                ldm4(b0,b1,b2,b3, sW + (16*jp*72 + bRowOff + ks*16)*2);
                mma_bf16(acc[2*jp],   a0,a1,a2,a3, b0,b1);
                mma_bf16(acc[2*jp+1], a0,a1,a2,a3, b2,b3);
            }
        }
    }

    const float gm = gamma[0];
    const int r0g = row0 + 16*w + gp, r1g = r0g + 8;
    #pragma unroll
    for (int j = 0; j < 16; j++) {
        int col = col0 + 8*j + 2*tg;
        float b0v = bo[col], b1v = bo[col+1];
        float2 xv0 = *(const float2*)(x + (size_t)r0g*256 + col);
        float2 ov0 = make_float2(gm*(acc[j][0]+b0v) + xv0.x, gm*(acc[j][1]+b1v) + xv0.y);
        *(float2*)(out + (size_t)r0g*256 + col) = ov0;
        float2 xv1 = *(const float2*)(x + (size_t)r1g*256 + col);
        float2 ov1 = make_float2(gm*(acc[j][2]+b0v) + xv1.x, gm*(acc[j][3]+b1v) + xv1.y);
        *(float2*)(out + (size_t)r1g*256 + col) = ov1;
    }
}

// ---------------- launch ----------------
extern "C" void kernel_launch(void* const* d_in, const int* in_sizes, int n_in,
                              void* d_out, int out_size)
{
    (void)in_sizes; (void)n_in; (void)out_size;
    const float* x     = (const float*)d_in[0];
    const float* Wf    = (const float*)d_in[1];
    const float* bfv   = (const float*)d_in[2];
    const float* Wg    = (const float*)d_in[3];
    const float* bg    = (const float*)d_in[4];
    const float* Wh    = (const float*)d_in[5];
    const float* bh    = (const float*)d_in[6];
    const float* Wo    = (const float*)d_in[7];
    const float* bo    = (const float*)d_in[8];
    const float* gamma = (const float*)d_in[9];
    float* out = (float*)d_out;

    prep_k<<<192, 256>>>(Wf, Wg, Wh, Wo);
    proj_k<<<NPIX/128, 256>>>(x, bg, bfv, bh);
    pool_f_k<<<512, 256>>>();
    pool_h_k<<<2048, 256>>>();
    attn_k<<<NPIX/128, 256>>>();
    out_k<<<(NPIX/128)*2, 256>>>(x, bo, gamma, out);
}

// round 7
// speedup vs baseline: 5.5693x; 1.0938x over previous
#include <cuda_runtime.h>
#include <cuda_bf16.h>
#include <cstdint>

#define NB 4096
#define MB 1024
#define BATCH 8
#define NPIX (BATCH*NB)   // 32768

// ---------------- scratch (bf16) ----------------
__device__ __nv_bfloat16 g_wt[192*256];            // [n][k] transposed Wg|Wf|Wh
__device__ __nv_bfloat16 g_wot[256*128];           // [n][k] transposed Wo
__device__ __nv_bfloat16 g_gb[(size_t)NPIX*32];    // g [row][32]
__device__ __nv_bfloat16 g_fp[BATCH*MB*32];        // f pooled [b*M][32]
__device__ __nv_bfloat16 g_ht[BATCH*128*MB];       // h pooled TRANSPOSED [b][c][m]
__device__ __nv_bfloat16 g_obf[(size_t)NPIX*128];  // attention out [row][128]

// ---------------- helpers ----------------
__device__ __forceinline__ uint32_t packbf(float lo, float hi) {
    __nv_bfloat162 h = __float22bfloat162_rn(make_float2(lo, hi));
    return *reinterpret_cast<uint32_t*>(&h);
}
__device__ __forceinline__ void mma_bf16(float* c,
    uint32_t a0, uint32_t a1, uint32_t a2, uint32_t a3,
    uint32_t b0, uint32_t b1)
{
    asm volatile(
        "mma.sync.aligned.m16n8k16.row.col.f32.bf16.bf16.f32 "
        "{%0,%1,%2,%3},{%4,%5,%6,%7},{%8,%9},{%0,%1,%2,%3};\n"
        : "+f"(c[0]), "+f"(c[1]), "+f"(c[2]), "+f"(c[3])
        : "r"(a0), "r"(a1), "r"(a2), "r"(a3), "r"(b0), "r"(b1));
}
__device__ __forceinline__ void ldm4(uint32_t& r0, uint32_t& r1, uint32_t& r2, uint32_t& r3,
                                     uint32_t addr)
{
    asm volatile("ldmatrix.sync.aligned.m8n8.x4.shared.b16 {%0,%1,%2,%3}, [%4];\n"
                 : "=r"(r0), "=r"(r1), "=r"(r2), "=r"(r3) : "r"(addr));
}
__device__ __forceinline__ void cp16(uint32_t smem_dst, const void* gsrc)
{
    asm volatile("cp.async.cg.shared.global [%0], [%1], 16;\n"
                 :: "r"(smem_dst), "l"(gsrc) : "memory");
}
__device__ __forceinline__ void cp_commit()
{
    asm volatile("cp.async.commit_group;\n" ::: "memory");
}
__device__ __forceinline__ void cp_wait1()
{
    asm volatile("cp.async.wait_group 1;\n" ::: "memory");
}

// ---------------- prep: transpose + convert weights ----------------
__global__ void prep_k(const float* __restrict__ Wf, const float* __restrict__ Wg,
                       const float* __restrict__ Wh, const float* __restrict__ Wo)
{
    int idx = blockIdx.x * 256 + threadIdx.x;     // 192 blocks -> 49152
    if (idx < 192*256) {
        int n = idx >> 8, k = idx & 255;
        float v = (n < 32) ? Wg[k*32 + n] : (n < 64) ? Wf[k*32 + (n-32)] : Wh[k*128 + (n-64)];
        g_wt[idx] = __float2bfloat16(v);
    }
    if (idx < 256*128) {
        int n = idx >> 7, k = idx & 127;
        g_wot[idx] = __float2bfloat16(Wo[k*256 + n]);
    }
}

// ---------------- projection + fused 2x2 pooling ----------------
// block 128 rows x 192 cols; 8 warps x 16-row stripes.
// 128 rows = exactly one h-row pair {2t, 2t+1} of one batch -> pool f,h in-block.
// smem union: GEMM phase Xs[128*20]+Ws[192*20]=6400 u32; pool phase Pf[128*17]+Ph[128*66]=10624 u32.
__global__ void __launch_bounds__(256) proj_k(const float* __restrict__ X,
    const float* __restrict__ bg, const float* __restrict__ bfv, const float* __restrict__ bh)
{
    __shared__ uint32_t psm[10624];
    uint32_t* Xs = psm;          // [128][20]
    uint32_t* Ws = psm + 2560;   // [192][20]
    uint32_t* Pf = psm;          // [128][17]  (pool phase)
    uint32_t* Ph = psm + 2176;   // [128][66]
    const int tid = threadIdx.x, lane = tid & 31, w = tid >> 5;
    const int gp = lane >> 2, tg = lane & 3, l8 = lane & 7, gq = lane >> 3;
    const int row0 = blockIdx.x * 128;

    float acc[24][4];
    #pragma unroll
    for (int j = 0; j < 24; j++)
        #pragma unroll
        for (int i = 0; i < 4; i++) acc[j][i] = 0.f;

    const uint32_t sX = (uint32_t)__cvta_generic_to_shared(Xs);
    const uint32_t sW = (uint32_t)__cvta_generic_to_shared(Ws);
    const uint32_t aOff = sX + ((16*w + l8 + 8*(gq&1))*40 + 8*(gq>>1))*2;
    const uint32_t bRowOff = (l8 + 8*(gq>>1))*40 + 8*(gq&1);

    for (int kc = 0; kc < 256; kc += 32) {
        __syncthreads();
        #pragma unroll
        for (int t = 0; t < 4; t++) {
            int idx = t*256 + tid; int rr = idx >> 3, q = idx & 7;
            float4 v = *(const float4*)(X + (size_t)(row0+rr)*256 + kc + q*4);
            Xs[rr*20 + q*2]     = packbf(v.x, v.y);
            Xs[rr*20 + q*2 + 1] = packbf(v.z, v.w);
        }
        const uint4* wsrc = (const uint4*)g_wt;
        #pragma unroll
        for (int t = 0; t < 3; t++) {
            int idx = t*256 + tid; int rr = idx >> 2, q = idx & 3;
            uint4 v = wsrc[(size_t)rr*32 + (kc>>3) + q];
            *(uint4*)&Ws[rr*20 + q*4] = v;
        }
        __syncthreads();
        #pragma unroll
        for (int ks = 0; ks < 2; ks++) {
            uint32_t a0,a1,a2,a3;
            ldm4(a0,a1,a2,a3, aOff + ks*32);
            #pragma unroll
            for (int jp = 0; jp < 12; jp++) {
                uint32_t b0,b1,b2,b3;
                ldm4(b0,b1,b2,b3, sW + (16*jp*40 + bRowOff + ks*16)*2);
                mma_bf16(acc[2*jp],   a0,a1,a2,a3, b0,b1);
                mma_bf16(acc[2*jp+1], a0,a1,a2,a3, b2,b3);
            }
        }
    }

    // ---- epilogue: g direct to global; f,h into smem pool buffers ----
    __syncthreads();   // all mma reads of Xs/Ws done before overwrite
    const int r0l = 16*w + gp, r1l = r0l + 8;
    const int r0g = row0 + r0l, r1g = row0 + r1l;
    uint32_t* gout = (uint32_t*)g_gb;
    #pragma unroll
    for (int j = 0; j < 24; j++) {
        int nb = 8*j, cp = nb + 2*tg;
        if (nb < 32) {
            float b0v = bg[cp], b1v = bg[cp+1];
            gout[(size_t)r0g*16 + (cp>>1)] = packbf(acc[j][0]+b0v, acc[j][1]+b1v);
            gout[(size_t)r1g*16 + (cp>>1)] = packbf(acc[j][2]+b0v, acc[j][3]+b1v);
        } else if (nb < 64) {
            int c = cp - 32;
            float b0v = bfv[c], b1v = bfv[c+1];
            Pf[r0l*17 + (c>>1)] = packbf(acc[j][0]+b0v, acc[j][1]+b1v);
            Pf[r1l*17 + (c>>1)] = packbf(acc[j][2]+b0v, acc[j][3]+b1v);
        } else {
            int c = cp - 64;
            float b0v = bh[c], b1v = bh[c+1];
            Ph[r0l*66 + (c>>1)] = packbf(acc[j][0]+b0v, acc[j][1]+b1v);
            Ph[r1l*66 + (c>>1)] = packbf(acc[j][2]+b0v, acc[j][3]+b1v);
        }
    }
    __syncthreads();

    // ---- pool 2x2 from smem ----
    const int b0i = row0 >> 12;                  // batch
    const int tpair = (row0 & 4095) >> 7;        // h-row pair index (0..31)
    // f: 32 m-rows x 16 u32
    for (int it = tid; it < 512; it += 256) {
        int c2 = it & 15, w2 = it >> 4;
        uint32_t u00 = Pf[(2*w2)*17 + c2];
        uint32_t u01 = Pf[(2*w2+1)*17 + c2];
        uint32_t u10 = Pf[(64+2*w2)*17 + c2];
        uint32_t u11 = Pf[(64+2*w2+1)*17 + c2];
        __nv_bfloat162 v = __hmax2(__hmax2(*(__nv_bfloat162*)&u00, *(__nv_bfloat162*)&u01),
                                   __hmax2(*(__nv_bfloat162*)&u10, *(__nv_bfloat162*)&u11));
        ((uint32_t*)g_fp)[((size_t)b0i*MB + tpair*32 + w2)*16 + c2] = *(uint32_t*)&v;
    }
    // h: 64 channel-pairs x 16 m-pairs, transposed out [b][c][m>>1]
    for (int it = tid; it < 1024; it += 256) {
        int u = it & 15, c2 = it >> 4;           // c2: channel pair 0..63, u: m-pair 0..15
        int w2a = 2*u, w2b = 2*u + 1;
        uint32_t a0 = Ph[(2*w2a)*66 + c2],    a1 = Ph[(2*w2a+1)*66 + c2];
        uint32_t a2 = Ph[(64+2*w2a)*66 + c2], a3 = Ph[(64+2*w2a+1)*66 + c2];
        __nv_bfloat162 pa = __hmax2(__hmax2(*(__nv_bfloat162*)&a0, *(__nv_bfloat162*)&a1),
                                    __hmax2(*(__nv_bfloat162*)&a2, *(__nv_bfloat162*)&a3));
        uint32_t b0u = Ph[(2*w2b)*66 + c2],    b1u = Ph[(2*w2b+1)*66 + c2];
        uint32_t b2u = Ph[(64+2*w2b)*66 + c2], b3u = Ph[(64+2*w2b+1)*66 + c2];
        __nv_bfloat162 pb = __hmax2(__hmax2(*(__nv_bfloat162*)&b0u, *(__nv_bfloat162*)&b1u),
                                    __hmax2(*(__nv_bfloat162*)&b2u, *(__nv_bfloat162*)&b3u));
        __nv_bfloat162 lo = __halves2bfloat162(__low2bfloat16(pa),  __low2bfloat16(pb));
        __nv_bfloat162 hi = __halves2bfloat162(__high2bfloat16(pa), __high2bfloat16(pb));
        size_t dst = ((size_t)(b0i*128 + 2*c2))*512 + tpair*16 + u;
        ((uint32_t*)g_ht)[dst]       = *(uint32_t*)&lo;
        ((uint32_t*)g_ht)[dst + 512] = *(uint32_t*)&hi;
    }
}

// ---------------- flash attention, bf16 mma, cp.async 3-stage pipeline ----------------
// block = 128 queries x 1024 keys (16 tiles of 64). 8 warps x 16-row stripes.
// dynamic smem (u32): Gs[2560] | Fs[3][1280] | Hs[3][4608]  = 20224 u32 = 80896 B
#define ATTN_SMEM_BYTES 80896

__global__ void __launch_bounds__(256) attn_k()
{
    extern __shared__ uint32_t dsm[];
    const int tid = threadIdx.x, lane = tid & 31, w = tid >> 5;
    const int gp = lane >> 2, tg = lane & 3, l8 = lane & 7, gq = lane >> 3;
    const int b = blockIdx.x >> 5, q0 = (blockIdx.x & 31)*128;

    const uint32_t sBase = (uint32_t)__cvta_generic_to_shared(dsm);
    const uint32_t sG = sBase;
    uint32_t sF[3], sH[3];
    #pragma unroll
    for (int i = 0; i < 3; i++) {
        sF[i] = sBase + (2560 + i*1280)*4;
        sH[i] = sBase + (6400 + i*4608)*4;
    }

    const uint32_t* gsrc = (const uint32_t*)g_gb + ((size_t)b*NB + q0)*16;
    const uint32_t* fbase = (const uint32_t*)g_fp + (size_t)b*MB*16;
    const uint32_t* hbase = (const uint32_t*)g_ht + (size_t)b*128*512;

    // prefetch group 0: Gs + tile0;  group 1: tile1
    {
        #pragma unroll
        for (int t = 0; t < 2; t++) {
            int idx = t*256 + tid; int rr = idx >> 2, q4 = idx & 3;
            cp16(sG + (rr*20 + q4*4)*4, gsrc + (size_t)rr*16 + q4*4);
        }
        // tile 0
        { int rr = tid >> 2, q4 = tid & 3;
          cp16(sF[0] + (rr*20 + q4*4)*4, fbase + (size_t)rr*16 + q4*4); }
        #pragma unroll
        for (int t = 0; t < 4; t++) {
            int idx = t*256 + tid; int rr = idx >> 3, q4 = idx & 7;
            cp16(sH[0] + (rr*36 + q4*4)*4, hbase + (size_t)rr*512 + q4*4);
        }
        cp_commit();
        // tile 1
        { int rr = tid >> 2, q4 = tid & 3;
          cp16(sF[1] + (rr*20 + q4*4)*4, fbase + (size_t)(64+rr)*16 + q4*4); }
        #pragma unroll
        for (int t = 0; t < 4; t++) {
            int idx = t*256 + tid; int rr = idx >> 3, q4 = idx & 7;
            cp16(sH[1] + (rr*36 + q4*4)*4, hbase + (size_t)rr*512 + 32 + q4*4);
        }
        cp_commit();
    }

    const uint32_t aOff = sG + ((16*w + l8 + 8*(gq&1))*40 + 8*(gq>>1))*2;
    const uint32_t bRow40 = (l8 + 8*(gq>>1))*40 + 8*(gq&1);
    const uint32_t bRow72 = (l8 + 8*(gq>>1))*72 + 8*(gq&1);

    float m0v = -1e30f, m1v = -1e30f, l0v = 0.f, l1v = 0.f;
    float o[16][4];
    #pragma unroll
    for (int j = 0; j < 16; j++)
        #pragma unroll
        for (int i = 0; i < 4; i++) o[j][i] = 0.f;

    #pragma unroll 1
    for (int kt = 0; kt < 16; kt++) {
        const int ib = kt % 3;
        cp_wait1();            // tile kt arrived (newest group = kt+1 may be in flight)
        __syncthreads();       // visibility + all warps done with tile kt-1's buffer

        // prefetch tile kt+2 into buffer (kt+2)%3 (free: held kt-1, consumed above)
        {
            const int kt2 = kt + 2;
            if (kt2 < 16) {
                const int ib2 = kt2 % 3;
                int rr = tid >> 2, q4 = tid & 3;
                cp16(sF[ib2] + (rr*20 + q4*4)*4, fbase + (size_t)(kt2*64 + rr)*16 + q4*4);
                #pragma unroll
                for (int t = 0; t < 4; t++) {
                    int idx = t*256 + tid; int hr = idx >> 3, hq = idx & 7;
                    cp16(sH[ib2] + (hr*36 + hq*4)*4, hbase + (size_t)hr*512 + kt2*32 + hq*4);
                }
            }
            cp_commit();       // commit every iteration (possibly empty) -> uniform wait_group 1
        }

        // S = G @ F^T
        float s[8][4];
        #pragma unroll
        for (int j = 0; j < 8; j++)
            #pragma unroll
            for (int i = 0; i < 4; i++) s[j][i] = 0.f;
        #pragma unroll
        for (int ks = 0; ks < 2; ks++) {
            uint32_t a0,a1,a2,a3;
            ldm4(a0,a1,a2,a3, aOff + ks*32);
            #pragma unroll
            for (int jp = 0; jp < 4; jp++) {
                uint32_t b0,b1,b2,b3;
                ldm4(b0,b1,b2,b3, sF[ib] + (16*jp*40 + bRow40 + ks*16)*2);
                mma_bf16(s[2*jp],   a0,a1,a2,a3, b0,b1);
                mma_bf16(s[2*jp+1], a0,a1,a2,a3, b2,b3);
            }
        }

        // online softmax
        {
            float tm = -1e30f;
            #pragma unroll
            for (int j = 0; j < 8; j++) tm = fmaxf(tm, fmaxf(s[j][0], s[j][1]));
            tm = fmaxf(tm, __shfl_xor_sync(0xffffffffu, tm, 1));
            tm = fmaxf(tm, __shfl_xor_sync(0xffffffffu, tm, 2));
            float mn = fmaxf(m0v, tm);
            float corr = __expf(m0v - mn);
            m0v = mn;
            float rs = 0.f;
            #pragma unroll
            for (int j = 0; j < 8; j++) {
                s[j][0] = __expf(s[j][0] - mn);
                s[j][1] = __expf(s[j][1] - mn);
                rs += s[j][0] + s[j][1];
            }
            rs += __shfl_xor_sync(0xffffffffu, rs, 1);
            rs += __shfl_xor_sync(0xffffffffu, rs, 2);
            l0v = l0v * corr + rs;
            #pragma unroll
            for (int j = 0; j < 16; j++) { o[j][0] *= corr; o[j][1] *= corr; }
        }
        {
            float tm = -1e30f;
            #pragma unroll
            for (int j = 0; j < 8; j++) tm = fmaxf(tm, fmaxf(s[j][2], s[j][3]));
            tm = fmaxf(tm, __shfl_xor_sync(0xffffffffu, tm, 1));
            tm = fmaxf(tm, __shfl_xor_sync(0xffffffffu, tm, 2));
            float mn = fmaxf(m1v, tm);
            float corr = __expf(m1v - mn);
            m1v = mn;
            float rs = 0.f;
            #pragma unroll
            for (int j = 0; j < 8; j++) {
                s[j][2] = __expf(s[j][2] - mn);
                s[j][3] = __expf(s[j][3] - mn);
                rs += s[j][2] + s[j][3];
            }
            rs += __shfl_xor_sync(0xffffffffu, rs, 1);
            rs += __shfl_xor_sync(0xffffffffu, rs, 2);
            l1v = l1v * corr + rs;
            #pragma unroll
            for (int j = 0; j < 16; j++) { o[j][2] *= corr; o[j][3] *= corr; }
        }

        // P -> bf16 A fragments (register-direct)
        uint32_t pa[4][4];
        #pragma unroll
        for (int ks = 0; ks < 4; ks++) {
            pa[ks][0] = packbf(s[2*ks][0],   s[2*ks][1]);
            pa[ks][1] = packbf(s[2*ks][2],   s[2*ks][3]);
            pa[ks][2] = packbf(s[2*ks+1][0], s[2*ks+1][1]);
            pa[ks][3] = packbf(s[2*ks+1][2], s[2*ks+1][3]);
        }

        // O += P @ H
        #pragma unroll
        for (int jp = 0; jp < 8; jp++) {
            #pragma unroll
            for (int ks = 0; ks < 4; ks++) {
                uint32_t b0,b1,b2,b3;
                ldm4(b0,b1,b2,b3, sH[ib] + (16*jp*72 + bRow72 + ks*16)*2);
                mma_bf16(o[2*jp],   pa[ks][0],pa[ks][1],pa[ks][2],pa[ks][3], b0,b1);
                mma_bf16(o[2*jp+1], pa[ks][0],pa[ks][1],pa[ks][2],pa[ks][3], b2,b3);
            }
        }
    }

    // epilogue: normalize, store bf16
    const float inv0 = 1.f / l0v, inv1 = 1.f / l1v;
    uint32_t* osink = (uint32_t*)g_obf;
    const int r0g = b*NB + q0 + 16*w + gp, r1g = r0g + 8;
    #pragma unroll
    for (int j = 0; j < 16; j++) {
        osink[(size_t)r0g*64 + 4*j + tg] = packbf(o[j][0]*inv0, o[j][1]*inv0);
        osink[(size_t)r1g*64 + 4*j + tg] = packbf(o[j][2]*inv1, o[j][3]*inv1);
    }
}

// ---------------- out = gamma * (O @ Wo + bo) + x ----------------
__global__ void __launch_bounds__(256) out_k(const float* __restrict__ x,
    const float* __restrict__ bo, const float* __restrict__ gamma,
    float* __restrict__ out)
{
    __shared__ uint32_t Os[128*36];   // bf16 [128][72]
    __shared__ uint32_t Wos[128*36];
    const int tid = threadIdx.x, lane = tid & 31, w = tid >> 5;
    const int gp = lane >> 2, tg = lane & 3, l8 = lane & 7, gq = lane >> 3;
    const int row0 = (blockIdx.x >> 1)*128, col0 = (blockIdx.x & 1)*128;

    float acc[16][4];
    #pragma unroll
    for (int j = 0; j < 16; j++)
        #pragma unroll
        for (int i = 0; i < 4; i++) acc[j][i] = 0.f;

    const uint32_t sO = (uint32_t)__cvta_generic_to_shared(Os);
    const uint32_t sW = (uint32_t)__cvta_generic_to_shared(Wos);
    const uint32_t aRowOff = (16*w + l8 + 8*(gq&1))*72 + 8*(gq>>1);
    const uint32_t bRowOff = (l8 + 8*(gq>>1))*72 + 8*(gq&1);

    for (int kc = 0; kc < 128; kc += 64) {
        __syncthreads();
        const uint32_t* osrc = (const uint32_t*)g_obf + (kc >> 1);
        #pragma unroll
        for (int t = 0; t < 16; t++) {
            int idx = t*256 + tid; int rr = idx >> 5, q = idx & 31;
            Os[rr*36 + q] = osrc[(size_t)(row0+rr)*64 + q];
        }
        const uint32_t* wsrc = (const uint32_t*)g_wot + (kc >> 1);
        #pragma unroll
        for (int t = 0; t < 16; t++) {
            int idx = t*256 + tid; int rr = idx >> 5, q = idx & 31;
            Wos[rr*36 + q] = wsrc[(size_t)(col0+rr)*64 + q];
        }
        __syncthreads();
        #pragma unroll
        for (int ks = 0; ks < 4; ks++) {
            uint32_t a0,a1,a2,a3;
            ldm4(a0,a1,a2,a3, sO + (aRowOff + ks*16)*2);
            #pragma unroll
            for (int jp = 0; jp < 8; jp++) {
                uint32_t b0,b1,b2,b3;
                ldm4(b0,b1,b2,b3, sW + (16*jp*72 + bRowOff + ks*16)*2);
                mma_bf16(acc[2*jp],   a0,a1,a2,a3, b0,b1);
                mma_bf16(acc[2*jp+1], a0,a1,a2,a3, b2,b3);
            }
        }
    }

    const float gm = gamma[0];
    const int r0g = row0 + 16*w + gp, r1g = r0g + 8;
    #pragma unroll
    for (int j = 0; j < 16; j++) {
        int col = col0 + 8*j + 2*tg;
        float b0v = bo[col], b1v = bo[col+1];
        float2 xv0 = *(const float2*)(x + (size_t)r0g*256 + col);
        float2 ov0 = make_float2(gm*(acc[j][0]+b0v) + xv0.x, gm*(acc[j][1]+b1v) + xv0.y);
        *(float2*)(out + (size_t)r0g*256 + col) = ov0;
        float2 xv1 = *(const float2*)(x + (size_t)r1g*256 + col);
        float2 ov1 = make_float2(gm*(acc[j][2]+b0v) + xv1.x, gm*(acc[j][3]+b1v) + xv1.y);
        *(float2*)(out + (size_t)r1g*256 + col) = ov1;
    }
}

// ---------------- launch ----------------
extern "C" void kernel_launch(void* const* d_in, const int* in_sizes, int n_in,
                              void* d_out, int out_size)
{
    (void)in_sizes; (void)n_in; (void)out_size;
    const float* x     = (const float*)d_in[0];
    const float* Wf    = (const float*)d_in[1];
    const float* bfv   = (const float*)d_in[2];
    const float* Wg    = (const float*)d_in[3];
    const float* bg    = (const float*)d_in[4];
    const float* Wh    = (const float*)d_in[5];
    const float* bh    = (const float*)d_in[6];
    const float* Wo    = (const float*)d_in[7];
    const float* bo    = (const float*)d_in[8];
    const float* gamma = (const float*)d_in[9];
    float* out = (float*)d_out;

    static bool attr_set = false;
    if (!attr_set) {
        cudaFuncSetAttribute(attn_k, cudaFuncAttributeMaxDynamicSharedMemorySize,
                             ATTN_SMEM_BYTES);
        attr_set = true;
    }

    prep_k<<<192, 256>>>(Wf, Wg, Wh, Wo);
    proj_k<<<NPIX/128, 256>>>(x, bg, bfv, bh);
    attn_k<<<NPIX/128, 256, ATTN_SMEM_BYTES>>>();
    out_k<<<(NPIX/128)*2, 256>>>(x, bo, gamma, out);
}

// round 8
// speedup vs baseline: 6.4593x; 1.1598x over previous
#include <cuda_runtime.h>
#include <cuda_bf16.h>
#include <cstdint>

#define NB 4096
#define MB 1024
#define BATCH 8
#define NPIX (BATCH*NB)   // 32768

// ---------------- scratch (bf16) ----------------
__device__ __nv_bfloat16 g_wt[192*256];            // [n][k] transposed Wg|Wf|Wh
__device__ __nv_bfloat16 g_wot[256*128];           // [n][k] transposed Wo
__device__ __nv_bfloat16 g_gb[(size_t)NPIX*32];    // g [row][32]
__device__ __nv_bfloat16 g_fp[BATCH*MB*32];        // f pooled [b*M][32]
__device__ __nv_bfloat16 g_ht[BATCH*128*MB];       // h pooled TRANSPOSED [b][c][m]
__device__ __nv_bfloat16 g_obf[(size_t)NPIX*128];  // attention out [row][128]

// ---------------- helpers ----------------
__device__ __forceinline__ uint32_t packbf(float lo, float hi) {
    __nv_bfloat162 h = __float22bfloat162_rn(make_float2(lo, hi));
    return *reinterpret_cast<uint32_t*>(&h);
}
__device__ __forceinline__ void mma_bf16(float* c,
    uint32_t a0, uint32_t a1, uint32_t a2, uint32_t a3,
    uint32_t b0, uint32_t b1)
{
    asm volatile(
        "mma.sync.aligned.m16n8k16.row.col.f32.bf16.bf16.f32 "
        "{%0,%1,%2,%3},{%4,%5,%6,%7},{%8,%9},{%0,%1,%2,%3};\n"
        : "+f"(c[0]), "+f"(c[1]), "+f"(c[2]), "+f"(c[3])
        : "r"(a0), "r"(a1), "r"(a2), "r"(a3), "r"(b0), "r"(b1));
}
__device__ __forceinline__ void ldm4(uint32_t& r0, uint32_t& r1, uint32_t& r2, uint32_t& r3,
                                     uint32_t addr)
{
    asm volatile("ldmatrix.sync.aligned.m8n8.x4.shared.b16 {%0,%1,%2,%3}, [%4];\n"
                 : "=r"(r0), "=r"(r1), "=r"(r2), "=r"(r3) : "r"(addr));
}
__device__ __forceinline__ void cp16(uint32_t smem_dst, const void* gsrc)
{
    asm volatile("cp.async.cg.shared.global [%0], [%1], 16;\n"
                 :: "r"(smem_dst), "l"(gsrc) : "memory");
}
__device__ __forceinline__ void cp_commit()
{
    asm volatile("cp.async.commit_group;\n" ::: "memory");
}
__device__ __forceinline__ void cp_wait1()
{
    asm volatile("cp.async.wait_group 1;\n" ::: "memory");
}
__device__ __forceinline__ void cp_wait0()
{
    asm volatile("cp.async.wait_group 0;\n" ::: "memory");
}

// ---------------- prep: transpose + convert weights ----------------
__global__ void prep_k(const float* __restrict__ Wf, const float* __restrict__ Wg,
                       const float* __restrict__ Wh, const float* __restrict__ Wo)
{
    int idx = blockIdx.x * 256 + threadIdx.x;     // 192 blocks -> 49152
    if (idx < 192*256) {
        int n = idx >> 8, k = idx & 255;
        float v = (n < 32) ? Wg[k*32 + n] : (n < 64) ? Wf[k*32 + (n-32)] : Wh[k*128 + (n-64)];
        g_wt[idx] = __float2bfloat16(v);
    }
    if (idx < 256*128) {
        int n = idx >> 7, k = idx & 127;
        g_wot[idx] = __float2bfloat16(Wo[k*256 + n]);
    }
}

// ---------------- projection + fused 2x2 pooling (register-prefetch pipeline) ----------------
// block 128 rows x 192 cols; 8 warps x 16-row stripes.
__global__ void __launch_bounds__(256) proj_k(const float* __restrict__ X,
    const float* __restrict__ bg, const float* __restrict__ bfv, const float* __restrict__ bh)
{
    __shared__ uint32_t psm[10624];
    uint32_t* Xs = psm;          // [128][20]
    uint32_t* Ws = psm + 2560;   // [192][20]
    uint32_t* Pf = psm;          // [128][17]  (pool phase)
    uint32_t* Ph = psm + 2176;   // [128][66]
    const int tid = threadIdx.x, lane = tid & 31, w = tid >> 5;
    const int gp = lane >> 2, tg = lane & 3, l8 = lane & 7, gq = lane >> 3;
    const int row0 = blockIdx.x * 128;

    float acc[24][4];
    #pragma unroll
    for (int j = 0; j < 24; j++)
        #pragma unroll
        for (int i = 0; i < 4; i++) acc[j][i] = 0.f;

    const uint32_t sX = (uint32_t)__cvta_generic_to_shared(Xs);
    const uint32_t sW = (uint32_t)__cvta_generic_to_shared(Ws);
    const uint32_t aOff = sX + ((16*w + l8 + 8*(gq&1))*40 + 8*(gq>>1))*2;
    const uint32_t bRowOff = (l8 + 8*(gq>>1))*40 + 8*(gq&1);

    const uint4* wsrc = (const uint4*)g_wt;

    // preload chunk 0 into registers
    float4 xr[4]; uint4 wr[3];
    #pragma unroll
    for (int t = 0; t < 4; t++) {
        int idx = t*256 + tid; int rr = idx >> 3, q = idx & 7;
        xr[t] = *(const float4*)(X + (size_t)(row0+rr)*256 + q*4);
    }
    #pragma unroll
    for (int t = 0; t < 3; t++) {
        int idx = t*256 + tid; int rr = idx >> 2, q = idx & 3;
        wr[t] = wsrc[(size_t)rr*32 + q];
    }

    for (int kc = 0; kc < 256; kc += 32) {
        // store staged registers to smem
        #pragma unroll
        for (int t = 0; t < 4; t++) {
            int idx = t*256 + tid; int rr = idx >> 3, q = idx & 7;
            Xs[rr*20 + q*2]     = packbf(xr[t].x, xr[t].y);
            Xs[rr*20 + q*2 + 1] = packbf(xr[t].z, xr[t].w);
        }
        #pragma unroll
        for (int t = 0; t < 3; t++) {
            int idx = t*256 + tid; int rr = idx >> 2, q = idx & 3;
            *(uint4*)&Ws[rr*20 + q*4] = wr[t];
        }
        // prefetch next chunk into registers (overlaps with mma below)
        if (kc + 32 < 256) {
            #pragma unroll
            for (int t = 0; t < 4; t++) {
                int idx = t*256 + tid; int rr = idx >> 3, q = idx & 7;
                xr[t] = *(const float4*)(X + (size_t)(row0+rr)*256 + kc + 32 + q*4);
            }
            #pragma unroll
            for (int t = 0; t < 3; t++) {
                int idx = t*256 + tid; int rr = idx >> 2, q = idx & 3;
                wr[t] = wsrc[(size_t)rr*32 + ((kc+32)>>3) + q];
            }
        }
        __syncthreads();
        #pragma unroll
        for (int ks = 0; ks < 2; ks++) {
            uint32_t a0,a1,a2,a3;
            ldm4(a0,a1,a2,a3, aOff + ks*32);
            #pragma unroll
            for (int jp = 0; jp < 12; jp++) {
                uint32_t b0,b1,b2,b3;
                ldm4(b0,b1,b2,b3, sW + (16*jp*40 + bRowOff + ks*16)*2);
                mma_bf16(acc[2*jp],   a0,a1,a2,a3, b0,b1);
                mma_bf16(acc[2*jp+1], a0,a1,a2,a3, b2,b3);
            }
        }
        __syncthreads();
    }

    // ---- epilogue: g direct to global; f,h into smem pool buffers ----
    const int r0l = 16*w + gp, r1l = r0l + 8;
    const int r0g = row0 + r0l, r1g = row0 + r1l;
    uint32_t* gout = (uint32_t*)g_gb;
    #pragma unroll
    for (int j = 0; j < 24; j++) {
        int nb = 8*j, cp = nb + 2*tg;
        if (nb < 32) {
            float b0v = bg[cp], b1v = bg[cp+1];
            gout[(size_t)r0g*16 + (cp>>1)] = packbf(acc[j][0]+b0v, acc[j][1]+b1v);
            gout[(size_t)r1g*16 + (cp>>1)] = packbf(acc[j][2]+b0v, acc[j][3]+b1v);
        } else if (nb < 64) {
            int c = cp - 32;
            float b0v = bfv[c], b1v = bfv[c+1];
            Pf[r0l*17 + (c>>1)] = packbf(acc[j][0]+b0v, acc[j][1]+b1v);
            Pf[r1l*17 + (c>>1)] = packbf(acc[j][2]+b0v, acc[j][3]+b1v);
        } else {
            int c = cp - 64;
            float b0v = bh[c], b1v = bh[c+1];
            Ph[r0l*66 + (c>>1)] = packbf(acc[j][0]+b0v, acc[j][1]+b1v);
            Ph[r1l*66 + (c>>1)] = packbf(acc[j][2]+b0v, acc[j][3]+b1v);
        }
    }
    __syncthreads();

    // ---- pool 2x2 from smem ----
    const int b0i = row0 >> 12;                  // batch
    const int tpair = (row0 & 4095) >> 7;        // h-row pair index (0..31)
    // f: 32 m-rows x 16 u32
    for (int it = tid; it < 512; it += 256) {
        int c2 = it & 15, w2 = it >> 4;
        uint32_t u00 = Pf[(2*w2)*17 + c2];
        uint32_t u01 = Pf[(2*w2+1)*17 + c2];
        uint32_t u10 = Pf[(64+2*w2)*17 + c2];
        uint32_t u11 = Pf[(64+2*w2+1)*17 + c2];
        __nv_bfloat162 v = __hmax2(__hmax2(*(__nv_bfloat162*)&u00, *(__nv_bfloat162*)&u01),
                                   __hmax2(*(__nv_bfloat162*)&u10, *(__nv_bfloat162*)&u11));
        ((uint32_t*)g_fp)[((size_t)b0i*MB + tpair*32 + w2)*16 + c2] = *(uint32_t*)&v;
    }
    // h: 64 channel-pairs x 16 m-pairs, transposed out [b][c][m>>1]
    for (int it = tid; it < 1024; it += 256) {
        int u = it & 15, c2 = it >> 4;
        int w2a = 2*u, w2b = 2*u + 1;
        uint32_t a0 = Ph[(2*w2a)*66 + c2],    a1 = Ph[(2*w2a+1)*66 + c2];
        uint32_t a2 = Ph[(64+2*w2a)*66 + c2], a3 = Ph[(64+2*w2a+1)*66 + c2];
        __nv_bfloat162 pa = __hmax2(__hmax2(*(__nv_bfloat162*)&a0, *(__nv_bfloat162*)&a1),
                                    __hmax2(*(__nv_bfloat162*)&a2, *(__nv_bfloat162*)&a3));
        uint32_t b0u = Ph[(2*w2b)*66 + c2],    b1u = Ph[(2*w2b+1)*66 + c2];
        uint32_t b2u = Ph[(64+2*w2b)*66 + c2], b3u = Ph[(64+2*w2b+1)*66 + c2];
        __nv_bfloat162 pb = __hmax2(__hmax2(*(__nv_bfloat162*)&b0u, *(__nv_bfloat162*)&b1u),
                                    __hmax2(*(__nv_bfloat162*)&b2u, *(__nv_bfloat162*)&b3u));
        __nv_bfloat162 lo = __halves2bfloat162(__low2bfloat16(pa),  __low2bfloat16(pb));
        __nv_bfloat162 hi = __halves2bfloat162(__high2bfloat16(pa), __high2bfloat16(pb));
        size_t dst = ((size_t)(b0i*128 + 2*c2))*512 + tpair*16 + u;
        ((uint32_t*)g_ht)[dst]       = *(uint32_t*)&lo;
        ((uint32_t*)g_ht)[dst + 512] = *(uint32_t*)&hi;
    }
}

// ---------------- flash attention, bf16 mma, cp.async 3-stage pipeline ----------------
#define ATTN_SMEM_BYTES 80896

__global__ void __launch_bounds__(256) attn_k()
{
    extern __shared__ uint32_t dsm[];
    const int tid = threadIdx.x, lane = tid & 31, w = tid >> 5;
    const int gp = lane >> 2, tg = lane & 3, l8 = lane & 7, gq = lane >> 3;
    const int b = blockIdx.x >> 5, q0 = (blockIdx.x & 31)*128;

    const uint32_t sBase = (uint32_t)__cvta_generic_to_shared(dsm);
    const uint32_t sG = sBase;
    uint32_t sF[3], sH[3];
    #pragma unroll
    for (int i = 0; i < 3; i++) {
        sF[i] = sBase + (2560 + i*1280)*4;
        sH[i] = sBase + (6400 + i*4608)*4;
    }

    const uint32_t* gsrc = (const uint32_t*)g_gb + ((size_t)b*NB + q0)*16;
    const uint32_t* fbase = (const uint32_t*)g_fp + (size_t)b*MB*16;
    const uint32_t* hbase = (const uint32_t*)g_ht + (size_t)b*128*512;

    {
        #pragma unroll
        for (int t = 0; t < 2; t++) {
            int idx = t*256 + tid; int rr = idx >> 2, q4 = idx & 3;
            cp16(sG + (rr*20 + q4*4)*4, gsrc + (size_t)rr*16 + q4*4);
        }
        { int rr = tid >> 2, q4 = tid & 3;
          cp16(sF[0] + (rr*20 + q4*4)*4, fbase + (size_t)rr*16 + q4*4); }
        #pragma unroll
        for (int t = 0; t < 4; t++) {
            int idx = t*256 + tid; int rr = idx >> 3, q4 = idx & 7;
            cp16(sH[0] + (rr*36 + q4*4)*4, hbase + (size_t)rr*512 + q4*4);
        }
        cp_commit();
        { int rr = tid >> 2, q4 = tid & 3;
          cp16(sF[1] + (rr*20 + q4*4)*4, fbase + (size_t)(64+rr)*16 + q4*4); }
        #pragma unroll
        for (int t = 0; t < 4; t++) {
            int idx = t*256 + tid; int rr = idx >> 3, q4 = idx & 7;
            cp16(sH[1] + (rr*36 + q4*4)*4, hbase + (size_t)rr*512 + 32 + q4*4);
        }
        cp_commit();
    }

    const uint32_t aOff = sG + ((16*w + l8 + 8*(gq&1))*40 + 8*(gq>>1))*2;
    const uint32_t bRow40 = (l8 + 8*(gq>>1))*40 + 8*(gq&1);
    const uint32_t bRow72 = (l8 + 8*(gq>>1))*72 + 8*(gq&1);

    float m0v = -1e30f, m1v = -1e30f, l0v = 0.f, l1v = 0.f;
    float o[16][4];
    #pragma unroll
    for (int j = 0; j < 16; j++)
        #pragma unroll
        for (int i = 0; i < 4; i++) o[j][i] = 0.f;

    #pragma unroll 1
    for (int kt = 0; kt < 16; kt++) {
        const int ib = kt % 3;
        cp_wait1();
        __syncthreads();

        {
            const int kt2 = kt + 2;
            if (kt2 < 16) {
                const int ib2 = kt2 % 3;
                int rr = tid >> 2, q4 = tid & 3;
                cp16(sF[ib2] + (rr*20 + q4*4)*4, fbase + (size_t)(kt2*64 + rr)*16 + q4*4);
                #pragma unroll
                for (int t = 0; t < 4; t++) {
                    int idx = t*256 + tid; int hr = idx >> 3, hq = idx & 7;
                    cp16(sH[ib2] + (hr*36 + hq*4)*4, hbase + (size_t)hr*512 + kt2*32 + hq*4);
                }
            }
            cp_commit();
        }

        float s[8][4];
        #pragma unroll
        for (int j = 0; j < 8; j++)
            #pragma unroll
            for (int i = 0; i < 4; i++) s[j][i] = 0.f;
        #pragma unroll
        for (int ks = 0; ks < 2; ks++) {
            uint32_t a0,a1,a2,a3;
            ldm4(a0,a1,a2,a3, aOff + ks*32);
            #pragma unroll
            for (int jp = 0; jp < 4; jp++) {
                uint32_t b0,b1,b2,b3;
                ldm4(b0,b1,b2,b3, sF[ib] + (16*jp*40 + bRow40 + ks*16)*2);
                mma_bf16(s[2*jp],   a0,a1,a2,a3, b0,b1);
                mma_bf16(s[2*jp+1], a0,a1,a2,a3, b2,b3);
            }
        }

        {
            float tm = -1e30f;
            #pragma unroll
            for (int j = 0; j < 8; j++) tm = fmaxf(tm, fmaxf(s[j][0], s[j][1]));
            tm = fmaxf(tm, __shfl_xor_sync(0xffffffffu, tm, 1));
            tm = fmaxf(tm, __shfl_xor_sync(0xffffffffu, tm, 2));
            float mn = fmaxf(m0v, tm);
            float corr = __expf(m0v - mn);
            m0v = mn;
            float rs = 0.f;
            #pragma unroll
            for (int j = 0; j < 8; j++) {
                s[j][0] = __expf(s[j][0] - mn);
                s[j][1] = __expf(s[j][1] - mn);
                rs += s[j][0] + s[j][1];
            }
            rs += __shfl_xor_sync(0xffffffffu, rs, 1);
            rs += __shfl_xor_sync(0xffffffffu, rs, 2);
            l0v = l0v * corr + rs;
            #pragma unroll
            for (int j = 0; j < 16; j++) { o[j][0] *= corr; o[j][1] *= corr; }
        }
        {
            float tm = -1e30f;
            #pragma unroll
            for (int j = 0; j < 8; j++) tm = fmaxf(tm, fmaxf(s[j][2], s[j][3]));
            tm = fmaxf(tm, __shfl_xor_sync(0xffffffffu, tm, 1));
            tm = fmaxf(tm, __shfl_xor_sync(0xffffffffu, tm, 2));
            float mn = fmaxf(m1v, tm);
            float corr = __expf(m1v - mn);
            m1v = mn;
            float rs = 0.f;
            #pragma unroll
            for (int j = 0; j < 8; j++) {
                s[j][2] = __expf(s[j][2] - mn);
                s[j][3] = __expf(s[j][3] - mn);
                rs += s[j][2] + s[j][3];
            }
            rs += __shfl_xor_sync(0xffffffffu, rs, 1);
            rs += __shfl_xor_sync(0xffffffffu, rs, 2);
            l1v = l1v * corr + rs;
            #pragma unroll
            for (int j = 0; j < 16; j++) { o[j][2] *= corr; o[j][3] *= corr; }
        }

        uint32_t pa[4][4];
        #pragma unroll
        for (int ks = 0; ks < 4; ks++) {
            pa[ks][0] = packbf(s[2*ks][0],   s[2*ks][1]);
            pa[ks][1] = packbf(s[2*ks][2],   s[2*ks][3]);
            pa[ks][2] = packbf(s[2*ks+1][0], s[2*ks+1][1]);
            pa[ks][3] = packbf(s[2*ks+1][2], s[2*ks+1][3]);
        }

        #pragma unroll
        for (int jp = 0; jp < 8; jp++) {
            #pragma unroll
            for (int ks = 0; ks < 4; ks++) {
                uint32_t b0,b1,b2,b3;
                ldm4(b0,b1,b2,b3, sH[ib] + (16*jp*72 + bRow72 + ks*16)*2);
                mma_bf16(o[2*jp],   pa[ks][0],pa[ks][1],pa[ks][2],pa[ks][3], b0,b1);
                mma_bf16(o[2*jp+1], pa[ks][0],pa[ks][1],pa[ks][2],pa[ks][3], b2,b3);
            }
        }
    }

    const float inv0 = 1.f / l0v, inv1 = 1.f / l1v;
    uint32_t* osink = (uint32_t*)g_obf;
    const int r0g = b*NB + q0 + 16*w + gp, r1g = r0g + 8;
    #pragma unroll
    for (int j = 0; j < 16; j++) {
        osink[(size_t)r0g*64 + 4*j + tg] = packbf(o[j][0]*inv0, o[j][1]*inv0);
        osink[(size_t)r1g*64 + 4*j + tg] = packbf(o[j][2]*inv1, o[j][3]*inv1);
    }
}

// ---------------- out = gamma * (O @ Wo + bo) + x  (single-phase cp.async) ----------------
// block 128 rows x 128 cols; full K=128 loaded once; pitch 68 u32 (conflict-free ldmatrix).
#define OUT_SMEM_BYTES (2*128*68*4)   // 69632

__global__ void __launch_bounds__(256,2) out_k(const float* __restrict__ x,
    const float* __restrict__ bo, const float* __restrict__ gamma,
    float* __restrict__ out)
{
    extern __shared__ uint32_t osm[];
    uint32_t* Os  = osm;             // [128][68]
    uint32_t* Wos = osm + 128*68;    // [128][68]
    const int tid = threadIdx.x, lane = tid & 31, w = tid >> 5;
    const int gp = lane >> 2, tg = lane & 3, l8 = lane & 7, gq = lane >> 3;
    const int row0 = (blockIdx.x >> 1)*128, col0 = (blockIdx.x & 1)*128;

    const uint32_t sO = (uint32_t)__cvta_generic_to_shared(Os);
    const uint32_t sW = (uint32_t)__cvta_generic_to_shared(Wos);

    // load both full tiles via cp.async (16 x 16B per thread, one group)
    const uint32_t* osrc = (const uint32_t*)g_obf;
    #pragma unroll
    for (int t = 0; t < 8; t++) {
        int idx = t*256 + tid; int rr = idx >> 4, q4 = idx & 15;
        cp16(sO + (rr*68 + q4*4)*4, osrc + (size_t)(row0+rr)*64 + q4*4);
    }
    const uint32_t* wsrc = (const uint32_t*)g_wot;
    #pragma unroll
    for (int t = 0; t < 8; t++) {
        int idx = t*256 + tid; int rr = idx >> 4, q4 = idx & 15;
        cp16(sW + (rr*68 + q4*4)*4, wsrc + (size_t)(col0+rr)*64 + q4*4);
    }
    cp_commit();

    float acc[16][4];
    #pragma unroll
    for (int j = 0; j < 16; j++)
        #pragma unroll
        for (int i = 0; i < 4; i++) acc[j][i] = 0.f;

    const uint32_t aRowOff = (16*w + l8 + 8*(gq&1))*136 + 8*(gq>>1);
    const uint32_t bRowOff = (l8 + 8*(gq>>1))*136 + 8*(gq&1);

    cp_wait0();
    __syncthreads();

    #pragma unroll
    for (int ks = 0; ks < 8; ks++) {
        uint32_t a0,a1,a2,a3;
        ldm4(a0,a1,a2,a3, sO + (aRowOff + ks*16)*2);
        #pragma unroll
        for (int jp = 0; jp < 8; jp++) {
            uint32_t b0,b1,b2,b3;
            ldm4(b0,b1,b2,b3, sW + (16*jp*136 + bRowOff + ks*16)*2);
            mma_bf16(acc[2*jp],   a0,a1,a2,a3, b0,b1);
            mma_bf16(acc[2*jp+1], a0,a1,a2,a3, b2,b3);
        }
    }

    const float gm = gamma[0];
    const int r0g = row0 + 16*w + gp, r1g = r0g + 8;
    #pragma unroll
    for (int j = 0; j < 16; j++) {
        int col = col0 + 8*j + 2*tg;
        float b0v = bo[col], b1v = bo[col+1];
        float2 xv0 = *(const float2*)(x + (size_t)r0g*256 + col);
        float2 ov0 = make_float2(gm*(acc[j][0]+b0v) + xv0.x, gm*(acc[j][1]+b1v) + xv0.y);
        *(float2*)(out + (size_t)r0g*256 + col) = ov0;
        float2 xv1 = *(const float2*)(x + (size_t)r1g*256 + col);
        float2 ov1 = make_float2(gm*(acc[j][2]+b0v) + xv1.x, gm*(acc[j][3]+b1v) + xv1.y);
        *(float2*)(out + (size_t)r1g*256 + col) = ov1;
    }
}

// ---------------- launch ----------------
extern "C" void kernel_launch(void* const* d_in, const int* in_sizes, int n_in,
                              void* d_out, int out_size)
{
    (void)in_sizes; (void)n_in; (void)out_size;
    const float* x     = (const float*)d_in[0];
    const float* Wf    = (const float*)d_in[1];
    const float* bfv   = (const float*)d_in[2];
    const float* Wg    = (const float*)d_in[3];
    const float* bg    = (const float*)d_in[4];
    const float* Wh    = (const float*)d_in[5];
    const float* bh    = (const float*)d_in[6];
    const float* Wo    = (const float*)d_in[7];
    const float* bo    = (const float*)d_in[8];
    const float* gamma = (const float*)d_in[9];
    float* out = (float*)d_out;

    static bool attr_set = false;
    if (!attr_set) {
        cudaFuncSetAttribute(attn_k, cudaFuncAttributeMaxDynamicSharedMemorySize,
                             ATTN_SMEM_BYTES);
        cudaFuncSetAttribute(out_k, cudaFuncAttributeMaxDynamicSharedMemorySize,
                             OUT_SMEM_BYTES);
        attr_set = true;
    }

    prep_k<<<192, 256>>>(Wf, Wg, Wh, Wo);
    proj_k<<<NPIX/128, 256>>>(x, bg, bfv, bh);
    attn_k<<<NPIX/128, 256, ATTN_SMEM_BYTES>>>();
    out_k<<<(NPIX/128)*2, 256, OUT_SMEM_BYTES>>>(x, bo, gamma, out);
}

// round 11
// speedup vs baseline: 6.4632x; 1.0006x over previous
#include <cuda_runtime.h>
#include <cuda_bf16.h>
#include <cstdint>

#define NB 4096
#define MB 1024
#define BATCH 8
#define NPIX (BATCH*NB)   // 32768

// ---------------- scratch (bf16) ----------------
__device__ __nv_bfloat16 g_wt[192*256];            // [n][k] transposed Wg|Wf|Wh
__device__ __nv_bfloat16 g_wot[256*128];           // [n][k] transposed Wo
__device__ __nv_bfloat16 g_gb[(size_t)NPIX*32];    // g [row][32]
__device__ __nv_bfloat16 g_fp[BATCH*MB*32];        // f pooled [b*M][32]
__device__ __nv_bfloat16 g_ht[BATCH*128*MB];       // h pooled TRANSPOSED [b][c][m]
__device__ __nv_bfloat16 g_obf[(size_t)NPIX*128];  // attention out [row][128]

// ---------------- helpers ----------------
__device__ __forceinline__ uint32_t packbf(float lo, float hi) {
    __nv_bfloat162 h = __float22bfloat162_rn(make_float2(lo, hi));
    return *reinterpret_cast<uint32_t*>(&h);
}
__device__ __forceinline__ void mma_bf16(float* c,
    uint32_t a0, uint32_t a1, uint32_t a2, uint32_t a3,
    uint32_t b0, uint32_t b1)
{
    asm volatile(
        "mma.sync.aligned.m16n8k16.row.col.f32.bf16.bf16.f32 "
        "{%0,%1,%2,%3},{%4,%5,%6,%7},{%8,%9},{%0,%1,%2,%3};\n"
        : "+f"(c[0]), "+f"(c[1]), "+f"(c[2]), "+f"(c[3])
        : "r"(a0), "r"(a1), "r"(a2), "r"(a3), "r"(b0), "r"(b1));
}
__device__ __forceinline__ void ldm4(uint32_t& r0, uint32_t& r1, uint32_t& r2, uint32_t& r3,
                                     uint32_t addr)
{
    asm volatile("ldmatrix.sync.aligned.m8n8.x4.shared.b16 {%0,%1,%2,%3}, [%4];\n"
                 : "=r"(r0), "=r"(r1), "=r"(r2), "=r"(r3) : "r"(addr));
}
__device__ __forceinline__ void cp16(uint32_t smem_dst, const void* gsrc)
{
    asm volatile("cp.async.cg.shared.global [%0], [%1], 16;\n"
                 :: "r"(smem_dst), "l"(gsrc) : "memory");
}
__device__ __forceinline__ void cp_commit()
{
    asm volatile("cp.async.commit_group;\n" ::: "memory");
}
__device__ __forceinline__ void cp_wait1()
{
    asm volatile("cp.async.wait_group 1;\n" ::: "memory");
}
__device__ __forceinline__ void cp_wait0()
{
    asm volatile("cp.async.wait_group 0;\n" ::: "memory");
}

// ---------------- prep: transpose + convert weights ----------------
__global__ void prep_k(const float* __restrict__ Wf, const float* __restrict__ Wg,
                       const float* __restrict__ Wh, const float* __restrict__ Wo)
{
    int idx = blockIdx.x * 256 + threadIdx.x;
    if (idx < 192*256) {
        int n = idx >> 8, k = idx & 255;
        float v = (n < 32) ? Wg[k*32 + n] : (n < 64) ? Wf[k*32 + (n-32)] : Wh[k*128 + (n-64)];
        g_wt[idx] = __float2bfloat16(v);
    }
    if (idx < 256*128) {
        int n = idx >> 7, k = idx & 127;
        g_wot[idx] = __float2bfloat16(Wo[k*256 + n]);
    }
}

// ---------------- projection + fused 2x2 pooling (register-prefetch pipeline) ----------------
__global__ void __launch_bounds__(256) proj_k(const float* __restrict__ X,
    const float* __restrict__ bg, const float* __restrict__ bfv, const float* __restrict__ bh)
{
    __shared__ uint32_t psm[10624];
    uint32_t* Xs = psm;          // [128][20]
    uint32_t* Ws = psm + 2560;   // [192][20]
    uint32_t* Pf = psm;          // [128][17]  (pool phase)
    uint32_t* Ph = psm + 2176;   // [128][66]
    const int tid = threadIdx.x, lane = tid & 31, w = tid >> 5;
    const int gp = lane >> 2, tg = lane & 3, l8 = lane & 7, gq = lane >> 3;
    const int row0 = blockIdx.x * 128;

    float acc[24][4];
    #pragma unroll
    for (int j = 0; j < 24; j++)
        #pragma unroll
        for (int i = 0; i < 4; i++) acc[j][i] = 0.f;

    const uint32_t sX = (uint32_t)__cvta_generic_to_shared(Xs);
    const uint32_t sW = (uint32_t)__cvta_generic_to_shared(Ws);
    const uint32_t aOff = sX + ((16*w + l8 + 8*(gq&1))*40 + 8*(gq>>1))*2;
    const uint32_t bRowOff = (l8 + 8*(gq>>1))*40 + 8*(gq&1);

    const uint4* wsrc = (const uint4*)g_wt;

    float4 xr[4]; uint4 wr[3];
    #pragma unroll
    for (int t = 0; t < 4; t++) {
        int idx = t*256 + tid; int rr = idx >> 3, q = idx & 7;
        xr[t] = *(const float4*)(X + (size_t)(row0+rr)*256 + q*4);
    }
    #pragma unroll
    for (int t = 0; t < 3; t++) {
        int idx = t*256 + tid; int rr = idx >> 2, q = idx & 3;
        wr[t] = wsrc[(size_t)rr*32 + q];
    }

    for (int kc = 0; kc < 256; kc += 32) {
        #pragma unroll
        for (int t = 0; t < 4; t++) {
            int idx = t*256 + tid; int rr = idx >> 3, q = idx & 7;
            Xs[rr*20 + q*2]     = packbf(xr[t].x, xr[t].y);
            Xs[rr*20 + q*2 + 1] = packbf(xr[t].z, xr[t].w);
        }
        #pragma unroll
        for (int t = 0; t < 3; t++) {
            int idx = t*256 + tid; int rr = idx >> 2, q = idx & 3;
            *(uint4*)&Ws[rr*20 + q*4] = wr[t];
        }
        if (kc + 32 < 256) {
            #pragma unroll
            for (int t = 0; t < 4; t++) {
                int idx = t*256 + tid; int rr = idx >> 3, q = idx & 7;
                xr[t] = *(const float4*)(X + (size_t)(row0+rr)*256 + kc + 32 + q*4);
            }
            #pragma unroll
            for (int t = 0; t < 3; t++) {
                int idx = t*256 + tid; int rr = idx >> 2, q = idx & 3;
                wr[t] = wsrc[(size_t)rr*32 + ((kc+32)>>3) + q];
            }
        }
        __syncthreads();
        #pragma unroll
        for (int ks = 0; ks < 2; ks++) {
            uint32_t a0,a1,a2,a3;
            ldm4(a0,a1,a2,a3, aOff + ks*32);
            #pragma unroll
            for (int jp = 0; jp < 12; jp++) {
                uint32_t b0,b1,b2,b3;
                ldm4(b0,b1,b2,b3, sW + (16*jp*40 + bRowOff + ks*16)*2);
                mma_bf16(acc[2*jp],   a0,a1,a2,a3, b0,b1);
                mma_bf16(acc[2*jp+1], a0,a1,a2,a3, b2,b3);
            }
        }
        __syncthreads();
    }

    const int r0l = 16*w + gp, r1l = r0l + 8;
    const int r0g = row0 + r0l, r1g = row0 + r1l;
    uint32_t* gout = (uint32_t*)g_gb;
    #pragma unroll
    for (int j = 0; j < 24; j++) {
        int nb = 8*j, cp = nb + 2*tg;
        if (nb < 32) {
            float b0v = bg[cp], b1v = bg[cp+1];
            gout[(size_t)r0g*16 + (cp>>1)] = packbf(acc[j][0]+b0v, acc[j][1]+b1v);
            gout[(size_t)r1g*16 + (cp>>1)] = packbf(acc[j][2]+b0v, acc[j][3]+b1v);
        } else if (nb < 64) {
            int c = cp - 32;
            float b0v = bfv[c], b1v = bfv[c+1];
            Pf[r0l*17 + (c>>1)] = packbf(acc[j][0]+b0v, acc[j][1]+b1v);
            Pf[r1l*17 + (c>>1)] = packbf(acc[j][2]+b0v, acc[j][3]+b1v);
        } else {
            int c = cp - 64;
            float b0v = bh[c], b1v = bh[c+1];
            Ph[r0l*66 + (c>>1)] = packbf(acc[j][0]+b0v, acc[j][1]+b1v);
            Ph[r1l*66 + (c>>1)] = packbf(acc[j][2]+b0v, acc[j][3]+b1v);
        }
    }
    __syncthreads();

    const int b0i = row0 >> 12;
    const int tpair = (row0 & 4095) >> 7;
    for (int it = tid; it < 512; it += 256) {
        int c2 = it & 15, w2 = it >> 4;
        uint32_t u00 = Pf[(2*w2)*17 + c2];
        uint32_t u01 = Pf[(2*w2+1)*17 + c2];
        uint32_t u10 = Pf[(64+2*w2)*17 + c2];
        uint32_t u11 = Pf[(64+2*w2+1)*17 + c2];
        __nv_bfloat162 v = __hmax2(__hmax2(*(__nv_bfloat162*)&u00, *(__nv_bfloat162*)&u01),
                                   __hmax2(*(__nv_bfloat162*)&u10, *(__nv_bfloat162*)&u11));
        ((uint32_t*)g_fp)[((size_t)b0i*MB + tpair*32 + w2)*16 + c2] = *(uint32_t*)&v;
    }
    for (int it = tid; it < 1024; it += 256) {
        int u = it & 15, c2 = it >> 4;
        int w2a = 2*u, w2b = 2*u + 1;
        uint32_t a0 = Ph[(2*w2a)*66 + c2],    a1 = Ph[(2*w2a+1)*66 + c2];
        uint32_t a2 = Ph[(64+2*w2a)*66 + c2], a3 = Ph[(64+2*w2a+1)*66 + c2];
        __nv_bfloat162 pa = __hmax2(__hmax2(*(__nv_bfloat162*)&a0, *(__nv_bfloat162*)&a1),
                                    __hmax2(*(__nv_bfloat162*)&a2, *(__nv_bfloat162*)&a3));
        uint32_t b0u = Ph[(2*w2b)*66 + c2],    b1u = Ph[(2*w2b+1)*66 + c2];
        uint32_t b2u = Ph[(64+2*w2b)*66 + c2], b3u = Ph[(64+2*w2b+1)*66 + c2];
        __nv_bfloat162 pb = __hmax2(__hmax2(*(__nv_bfloat162*)&b0u, *(__nv_bfloat162*)&b1u),
                                    __hmax2(*(__nv_bfloat162*)&b2u, *(__nv_bfloat162*)&b3u));
        __nv_bfloat162 lo = __halves2bfloat162(__low2bfloat16(pa),  __low2bfloat16(pb));
        __nv_bfloat162 hi = __halves2bfloat162(__high2bfloat16(pa), __high2bfloat16(pb));
        size_t dst = ((size_t)(b0i*128 + 2*c2))*512 + tpair*16 + u;
        ((uint32_t*)g_ht)[dst]       = *(uint32_t*)&lo;
        ((uint32_t*)g_ht)[dst + 512] = *(uint32_t*)&hi;
    }
}

// ---------------- flash attention (EXACT R7 known-good version) ----------------
#define ATTN_SMEM_BYTES 80896

__global__ void __launch_bounds__(256) attn_k()
{
    extern __shared__ uint32_t dsm[];
    const int tid = threadIdx.x, lane = tid & 31, w = tid >> 5;
    const int gp = lane >> 2, tg = lane & 3, l8 = lane & 7, gq = lane >> 3;
    const int b = blockIdx.x >> 5, q0 = (blockIdx.x & 31)*128;

    const uint32_t sBase = (uint32_t)__cvta_generic_to_shared(dsm);
    const uint32_t sG = sBase;
    uint32_t sF[3], sH[3];
    #pragma unroll
    for (int i = 0; i < 3; i++) {
        sF[i] = sBase + (2560 + i*1280)*4;
        sH[i] = sBase + (6400 + i*4608)*4;
    }

    const uint32_t* gsrc = (const uint32_t*)g_gb + ((size_t)b*NB + q0)*16;
    const uint32_t* fbase = (const uint32_t*)g_fp + (size_t)b*MB*16;
    const uint32_t* hbase = (const uint32_t*)g_ht + (size_t)b*128*512;

    {
        #pragma unroll
        for (int t = 0; t < 2; t++) {
            int idx = t*256 + tid; int rr = idx >> 2, q4 = idx & 3;
            cp16(sG + (rr*20 + q4*4)*4, gsrc + (size_t)rr*16 + q4*4);
        }
        { int rr = tid >> 2, q4 = tid & 3;
          cp16(sF[0] + (rr*20 + q4*4)*4, fbase + (size_t)rr*16 + q4*4); }
        #pragma unroll
        for (int t = 0; t < 4; t++) {
            int idx = t*256 + tid; int rr = idx >> 3, q4 = idx & 7;
            cp16(sH[0] + (rr*36 + q4*4)*4, hbase + (size_t)rr*512 + q4*4);
        }
        cp_commit();
        { int rr = tid >> 2, q4 = tid & 3;
          cp16(sF[1] + (rr*20 + q4*4)*4, fbase + (size_t)(64+rr)*16 + q4*4); }
        #pragma unroll
        for (int t = 0; t < 4; t++) {
            int idx = t*256 + tid; int rr = idx >> 3, q4 = idx & 7;
            cp16(sH[1] + (rr*36 + q4*4)*4, hbase + (size_t)rr*512 + 32 + q4*4);
        }
        cp_commit();
    }

    const uint32_t aOff = sG + ((16*w + l8 + 8*(gq&1))*40 + 8*(gq>>1))*2;
    const uint32_t bRow40 = (l8 + 8*(gq>>1))*40 + 8*(gq&1);
    const uint32_t bRow72 = (l8 + 8*(gq>>1))*72 + 8*(gq&1);

    float m0v = -1e30f, m1v = -1e30f, l0v = 0.f, l1v = 0.f;
    float o[16][4];
    #pragma unroll
    for (int j = 0; j < 16; j++)
        #pragma unroll
        for (int i = 0; i < 4; i++) o[j][i] = 0.f;

    #pragma unroll 1
    for (int kt = 0; kt < 16; kt++) {
        const int ib = kt % 3;
        cp_wait1();
        __syncthreads();

        {
            const int kt2 = kt + 2;
            if (kt2 < 16) {
                const int ib2 = kt2 % 3;
                int rr = tid >> 2, q4 = tid & 3;
                cp16(sF[ib2] + (rr*20 + q4*4)*4, fbase + (size_t)(kt2*64 + rr)*16 + q4*4);
                #pragma unroll
                for (int t = 0; t < 4; t++) {
                    int idx = t*256 + tid; int hr = idx >> 3, hq = idx & 7;
                    cp16(sH[ib2] + (hr*36 + hq*4)*4, hbase + (size_t)hr*512 + kt2*32 + hq*4);
                }
            }
            cp_commit();
        }

        float s[8][4];
        #pragma unroll
        for (int j = 0; j < 8; j++)
            #pragma unroll
            for (int i = 0; i < 4; i++) s[j][i] = 0.f;
        #pragma unroll
        for (int ks = 0; ks < 2; ks++) {
            uint32_t a0,a1,a2,a3;
            ldm4(a0,a1,a2,a3, aOff + ks*32);
            #pragma unroll
            for (int jp = 0; jp < 4; jp++) {
                uint32_t b0,b1,b2,b3;
                ldm4(b0,b1,b2,b3, sF[ib] + (16*jp*40 + bRow40 + ks*16)*2);
                mma_bf16(s[2*jp],   a0,a1,a2,a3, b0,b1);
                mma_bf16(s[2*jp+1], a0,a1,a2,a3, b2,b3);
            }
        }

        {
            float tm = -1e30f;
            #pragma unroll
            for (int j = 0; j < 8; j++) tm = fmaxf(tm, fmaxf(s[j][0], s[j][1]));
            tm = fmaxf(tm, __shfl_xor_sync(0xffffffffu, tm, 1));
            tm = fmaxf(tm, __shfl_xor_sync(0xffffffffu, tm, 2));
            float mn = fmaxf(m0v, tm);
            float corr = __expf(m0v - mn);
            m0v = mn;
            float rs = 0.f;
            #pragma unroll
            for (int j = 0; j < 8; j++) {
                s[j][0] = __expf(s[j][0] - mn);
                s[j][1] = __expf(s[j][1] - mn);
                rs += s[j][0] + s[j][1];
            }
            rs += __shfl_xor_sync(0xffffffffu, rs, 1);
            rs += __shfl_xor_sync(0xffffffffu, rs, 2);
            l0v = l0v * corr + rs;
            #pragma unroll
            for (int j = 0; j < 16; j++) { o[j][0] *= corr; o[j][1] *= corr; }
        }
        {
            float tm = -1e30f;
            #pragma unroll
            for (int j = 0; j < 8; j++) tm = fmaxf(tm, fmaxf(s[j][2], s[j][3]));
            tm = fmaxf(tm, __shfl_xor_sync(0xffffffffu, tm, 1));
            tm = fmaxf(tm, __shfl_xor_sync(0xffffffffu, tm, 2));
            float mn = fmaxf(m1v, tm);
            float corr = __expf(m1v - mn);
            m1v = mn;
            float rs = 0.f;
            #pragma unroll
            for (int j = 0; j < 8; j++) {
                s[j][2] = __expf(s[j][2] - mn);
                s[j][3] = __expf(s[j][3] - mn);
                rs += s[j][2] + s[j][3];
            }
            rs += __shfl_xor_sync(0xffffffffu, rs, 1);
            rs += __shfl_xor_sync(0xffffffffu, rs, 2);
            l1v = l1v * corr + rs;
            #pragma unroll
            for (int j = 0; j < 16; j++) { o[j][2] *= corr; o[j][3] *= corr; }
        }

        uint32_t pa[4][4];
        #pragma unroll
        for (int ks = 0; ks < 4; ks++) {
            pa[ks][0] = packbf(s[2*ks][0],   s[2*ks][1]);
            pa[ks][1] = packbf(s[2*ks][2],   s[2*ks][3]);
            pa[ks][2] = packbf(s[2*ks+1][0], s[2*ks+1][1]);
            pa[ks][3] = packbf(s[2*ks+1][2], s[2*ks+1][3]);
        }

        #pragma unroll
        for (int jp = 0; jp < 8; jp++) {
            #pragma unroll
            for (int ks = 0; ks < 4; ks++) {
                uint32_t b0,b1,b2,b3;
                ldm4(b0,b1,b2,b3, sH[ib] + (16*jp*72 + bRow72 + ks*16)*2);
                mma_bf16(o[2*jp],   pa[ks][0],pa[ks][1],pa[ks][2],pa[ks][3], b0,b1);
                mma_bf16(o[2*jp+1], pa[ks][0],pa[ks][1],pa[ks][2],pa[ks][3], b2,b3);
            }
        }
    }

    const float inv0 = 1.f / l0v, inv1 = 1.f / l1v;
    uint32_t* osink = (uint32_t*)g_obf;
    const int r0g = b*NB + q0 + 16*w + gp, r1g = r0g + 8;
    #pragma unroll
    for (int j = 0; j < 16; j++) {
        osink[(size_t)r0g*64 + 4*j + tg] = packbf(o[j][0]*inv0, o[j][1]*inv0);
        osink[(size_t)r1g*64 + 4*j + tg] = packbf(o[j][2]*inv1, o[j][3]*inv1);
    }
}

// ---------------- out = gamma * (O @ Wo + bo) + x ----------------
// 64 rows x 128 cols per block; warp w: rows 16*(w&3), col half 64*(w>>2).
// FIX (R9 bug): rows are 64 u32 of data (K=128 bf16), not 16 u32.
// Os fill: 64 rows x 64 u32 = 1024 cp16 (4/thread); Wos: 128 x 64 = 2048 (8/thread).
#define OUT_SMEM_BYTES ((64*68 + 128*68)*4)   // 52224

__global__ void __launch_bounds__(256,3) out_k(const float* __restrict__ x,
    const float* __restrict__ bo, const float* __restrict__ gamma,
    float* __restrict__ out)
{
    extern __shared__ uint32_t osm[];
    uint32_t* Os  = osm;             // [64][68]
    uint32_t* Wos = osm + 64*68;     // [128][68]
    const int tid = threadIdx.x, lane = tid & 31, w = tid >> 5;
    const int rw = w & 3, cw = w >> 2;
    const int gp = lane >> 2, tg = lane & 3, l8 = lane & 7, gq = lane >> 3;
    const int row0 = (blockIdx.x >> 1)*64, col0 = (blockIdx.x & 1)*128;

    const uint32_t sO = (uint32_t)__cvta_generic_to_shared(Os);
    const uint32_t sW = (uint32_t)__cvta_generic_to_shared(Wos);

    // O tile: 64 rows x 64 u32 (full K=128 bf16 per row)
    const uint32_t* osrc = (const uint32_t*)g_obf;
    #pragma unroll
    for (int t = 0; t < 4; t++) {
        int idx = t*256 + tid; int rr = idx >> 4, q4 = idx & 15;
        cp16(sO + (rr*68 + q4*4)*4, osrc + (size_t)(row0+rr)*64 + q4*4);
    }
    // W tile: 128 rows x 64 u32
    const uint32_t* wsrc = (const uint32_t*)g_wot;
    #pragma unroll
    for (int t = 0; t < 8; t++) {
        int idx = t*256 + tid; int rr = idx >> 4, q4 = idx & 15;
        cp16(sW + (rr*68 + q4*4)*4, wsrc + (size_t)(col0+rr)*64 + q4*4);
    }
    cp_commit();

    float acc[8][4];
    #pragma unroll
    for (int j = 0; j < 8; j++)
        #pragma unroll
        for (int i = 0; i < 4; i++) acc[j][i] = 0.f;

    const uint32_t aRowOff = (16*rw + l8 + 8*(gq&1))*136 + 8*(gq>>1);
    const uint32_t bRowOff = (l8 + 8*(gq>>1))*136 + 8*(gq&1);

    cp_wait0();
    __syncthreads();

    #pragma unroll
    for (int ks = 0; ks < 8; ks++) {
        uint32_t a0,a1,a2,a3;
        ldm4(a0,a1,a2,a3, sO + (aRowOff + ks*16)*2);
        #pragma unroll
        for (int jp = 0; jp < 4; jp++) {
            uint32_t b0,b1,b2,b3;
            ldm4(b0,b1,b2,b3, sW + (16*(4*cw + jp)*136 + bRowOff + ks*16)*2);
            mma_bf16(acc[2*jp],   a0,a1,a2,a3, b0,b1);
            mma_bf16(acc[2*jp+1], a0,a1,a2,a3, b2,b3);
        }
    }

    const float gm = gamma[0];
    const int r0g = row0 + 16*rw + gp, r1g = r0g + 8;
    const int colbase = col0 + 64*cw;
    #pragma unroll
    for (int j = 0; j < 8; j++) {
        int col = colbase + 8*j + 2*tg;
        float b0v = bo[col], b1v = bo[col+1];
        float2 xv0 = *(const float2*)(x + (size_t)r0g*256 + col);
        float2 ov0 = make_float2(gm*(acc[j][0]+b0v) + xv0.x, gm*(acc[j][1]+b1v) + xv0.y);
        *(float2*)(out + (size_t)r0g*256 + col) = ov0;
        float2 xv1 = *(const float2*)(x + (size_t)r1g*256 + col);
        float2 ov1 = make_float2(gm*(acc[j][2]+b0v) + xv1.x, gm*(acc[j][3]+b1v) + xv1.y);
        *(float2*)(out + (size_t)r1g*256 + col) = ov1;
    }
}

// ---------------- launch ----------------
extern "C" void kernel_launch(void* const* d_in, const int* in_sizes, int n_in,
                              void* d_out, int out_size)
{
    (void)in_sizes; (void)n_in; (void)out_size;
    const float* x     = (const float*)d_in[0];
    const float* Wf    = (const float*)d_in[1];
    const float* bfv   = (const float*)d_in[2];
    const float* Wg    = (const float*)d_in[3];
    const float* bg    = (const float*)d_in[4];
    const float* Wh    = (const float*)d_in[5];
    const float* bh    = (const float*)d_in[6];
    const float* Wo    = (const float*)d_in[7];
    const float* bo    = (const float*)d_in[8];
    const float* gamma = (const float*)d_in[9];
    float* out = (float*)d_out;

    static bool attr_set = false;
    if (!attr_set) {
        cudaFuncSetAttribute(attn_k, cudaFuncAttributeMaxDynamicSharedMemorySize,
                             ATTN_SMEM_BYTES);
        cudaFuncSetAttribute(out_k, cudaFuncAttributeMaxDynamicSharedMemorySize,
                             OUT_SMEM_BYTES);
        attr_set = true;
    }

    prep_k<<<192, 256>>>(Wf, Wg, Wh, Wo);
    proj_k<<<NPIX/128, 256>>>(x, bg, bfv, bh);
    attn_k<<<NPIX/128, 256, ATTN_SMEM_BYTES>>>();
    out_k<<<(NPIX/64)*2, 256, OUT_SMEM_BYTES>>>(x, bo, gamma, out);
}